// round 3
// baseline (speedup 1.0000x reference)
#include <cuda_runtime.h>
#include <cstdint>

// ---------------- problem constants ----------------
#define LNUM 6
#define HDIM 1024
#define ADIM 1024
#define IDIM 4096
#define BSZ  4
#define TSEQ 2048
#define MTOK (BSZ*TSEQ)          // 8192 tokens
#define NCHK 32                  // WKV chunks per sequence
#define CHLEN (TSEQ/NCHK)        // 64
#define NEGINF (-1e38f)

// ---------------- scratch (static device arrays; no allocations) ----------------
__device__ float g_h [(size_t)MTOK*HDIM];
__device__ float g_x [(size_t)MTOK*HDIM];
__device__ float g_k [(size_t)MTOK*ADIM];
__device__ float g_v [(size_t)MTOK*ADIM];
__device__ float g_r [(size_t)MTOK*ADIM];
__device__ float g_ry[(size_t)MTOK*ADIM];
__device__ float g_kk[(size_t)MTOK*IDIM];
__device__ float g_rr[(size_t)MTOK*HDIM];
__device__ float g_sA[BSZ*NCHK*ADIM];
__device__ float g_sB[BSZ*NCHK*ADIM];
__device__ float g_sP[BSZ*NCHK*ADIM];
__device__ float g_pA[BSZ*NCHK*ADIM];
__device__ float g_pB[BSZ*NCHK*ADIM];
__device__ float g_pP[BSZ*NCHK*ADIM];

// ---------------- layernorm ----------------
// one block per row, 256 threads, H=1024 (exactly 1 float4/thread)
__device__ __forceinline__ void ln_row_core(const float* __restrict__ src,
                                            const float* __restrict__ w,
                                            const float* __restrict__ b,
                                            float* __restrict__ dst)
{
    int tid = threadIdx.x;
    float4 xv = *(const float4*)(src + tid*4);
    float s = xv.x + xv.y + xv.z + xv.w;
    float q = xv.x*xv.x + xv.y*xv.y + xv.z*xv.z + xv.w*xv.w;
    #pragma unroll
    for (int o = 16; o > 0; o >>= 1) {
        s += __shfl_xor_sync(0xffffffffu, s, o);
        q += __shfl_xor_sync(0xffffffffu, q, o);
    }
    __shared__ float sh_s[8], sh_q[8];
    int wid = tid >> 5;
    if ((tid & 31) == 0) { sh_s[wid] = s; sh_q[wid] = q; }
    __syncthreads();
    float S = 0.f, Q = 0.f;
    #pragma unroll
    for (int i = 0; i < 8; i++) { S += sh_s[i]; Q += sh_q[i]; }
    float mu   = S * (1.0f/HDIM);
    float var  = Q * (1.0f/HDIM) - mu*mu;
    float rstd = rsqrtf(var + 1e-5f);
    float4 wv = *(const float4*)(w + tid*4);
    float4 bv = *(const float4*)(b + tid*4);
    float4 y;
    y.x = (xv.x - mu) * rstd * wv.x + bv.x;
    y.y = (xv.y - mu) * rstd * wv.y + bv.y;
    y.z = (xv.z - mu) * rstd * wv.z + bv.z;
    y.w = (xv.w - mu) * rstd * wv.w + bv.w;
    *(float4*)(dst + tid*4) = y;
}

__global__ void embed_ln_kernel(const int* __restrict__ ids,
                                const float* __restrict__ emb,
                                const float* __restrict__ w,
                                const float* __restrict__ b,
                                float* __restrict__ out)
{
    int row = blockIdx.x;
    int id  = ids[row];
    ln_row_core(emb + (size_t)id*HDIM, w, b, out + (size_t)row*HDIM);
}

__global__ void ln_kernel(const float* __restrict__ src,
                          const float* __restrict__ w,
                          const float* __restrict__ b,
                          float* __restrict__ dst)
{
    int row = blockIdx.x;
    ln_row_core(src + (size_t)row*HDIM, w, b, dst + (size_t)row*HDIM);
}

// ---------------- tiled SGEMM ----------------
// C[M,N] = epi( A'[M,K] @ W[N,K]^T )
// A' = A (AMIX=0)  or  mix[k]*A[m,k] + (1-mix[k])*A[m-1,k] (time-shift, AMIX=1)
// EPI: 0=store, 1=sigmoid, 2=relu^2, 3=C+=acc, 4=C+=gate*acc
// BM=BN=128, BK=8, 256 threads, 8x8 per thread. M fixed = MTOK, M%128==0, N%128==0, K%8==0.
template<int AMIX, int EPI>
__global__ __launch_bounds__(256) void gemm128(
    const float* __restrict__ Am, const float* __restrict__ Wm,
    const float* __restrict__ mix, const float* __restrict__ gate,
    float* __restrict__ C, int N, int K)
{
    __shared__ float As[8][128];
    __shared__ float Bs[8][128];
    const int tid = threadIdx.x;
    const int bm = blockIdx.y * 128;
    const int bn = blockIdx.x * 128;
    const int lr = tid >> 1;          // load row 0..127
    const int lc = (tid & 1) * 4;     // k offset 0 or 4
    const int ty = tid >> 4;          // 0..15
    const int tx = tid & 15;          // 0..15

    const float* Ap = Am + (size_t)(bm + lr) * K + lc;
    const float* Bp = Wm + (size_t)(bn + lr) * K + lc;
    const bool hasprev = AMIX ? (((bm + lr) % TSEQ) != 0) : false;
    const float* Pp = Ap - K;
    const float* Mp = mix + lc;

    float4 av, pv, mv, bv;
    av = *(const float4*)(Ap);
    bv = *(const float4*)(Bp);
    if (AMIX) {
        pv = hasprev ? *(const float4*)(Pp) : make_float4(0.f,0.f,0.f,0.f);
        mv = *(const float4*)(Mp);
    }

    float acc[8][8];
    #pragma unroll
    for (int i = 0; i < 8; i++)
        #pragma unroll
        for (int j = 0; j < 8; j++) acc[i][j] = 0.f;

    for (int k0 = 0; k0 < K; k0 += 8) {
        float4 a_st = av;
        if (AMIX) {
            a_st.x = mv.x*av.x + (1.f - mv.x)*pv.x;
            a_st.y = mv.y*av.y + (1.f - mv.y)*pv.y;
            a_st.z = mv.z*av.z + (1.f - mv.z)*pv.z;
            a_st.w = mv.w*av.w + (1.f - mv.w)*pv.w;
        }
        float4 b_st = bv;
        __syncthreads();
        As[lc+0][lr] = a_st.x; As[lc+1][lr] = a_st.y;
        As[lc+2][lr] = a_st.z; As[lc+3][lr] = a_st.w;
        Bs[lc+0][lr] = b_st.x; Bs[lc+1][lr] = b_st.y;
        Bs[lc+2][lr] = b_st.z; Bs[lc+3][lr] = b_st.w;
        __syncthreads();
        int kn = k0 + 8;
        if (kn < K) {  // prefetch next tile during compute
            av = *(const float4*)(Ap + kn);
            bv = *(const float4*)(Bp + kn);
            if (AMIX) {
                pv = hasprev ? *(const float4*)(Pp + kn) : make_float4(0.f,0.f,0.f,0.f);
                mv = *(const float4*)(Mp + kn);
            }
        }
        #pragma unroll
        for (int kk = 0; kk < 8; kk++) {
            float af[8], bf[8];
            *(float4*)(af)   = *(const float4*)(&As[kk][ty*8]);
            *(float4*)(af+4) = *(const float4*)(&As[kk][ty*8+4]);
            *(float4*)(bf)   = *(const float4*)(&Bs[kk][tx*8]);
            *(float4*)(bf+4) = *(const float4*)(&Bs[kk][tx*8+4]);
            #pragma unroll
            for (int i = 0; i < 8; i++)
                #pragma unroll
                for (int j = 0; j < 8; j++)
                    acc[i][j] = fmaf(af[i], bf[j], acc[i][j]);
        }
    }

    // epilogue
    #pragma unroll
    for (int i = 0; i < 8; i++) {
        size_t row = (size_t)(bm + ty*8 + i);
        float* crow = C + row * N + bn + tx*8;
        const float* grow = (EPI == 4) ? (gate + row * N + bn + tx*8) : nullptr;
        #pragma unroll
        for (int jj = 0; jj < 8; jj += 4) {
            float4 vv;
            vv.x = acc[i][jj+0]; vv.y = acc[i][jj+1];
            vv.z = acc[i][jj+2]; vv.w = acc[i][jj+3];
            if (EPI == 1) {
                vv.x = 1.f/(1.f + __expf(-vv.x));
                vv.y = 1.f/(1.f + __expf(-vv.y));
                vv.z = 1.f/(1.f + __expf(-vv.z));
                vv.w = 1.f/(1.f + __expf(-vv.w));
            } else if (EPI == 2) {
                float t;
                t = fmaxf(vv.x, 0.f); vv.x = t*t;
                t = fmaxf(vv.y, 0.f); vv.y = t*t;
                t = fmaxf(vv.z, 0.f); vv.z = t*t;
                t = fmaxf(vv.w, 0.f); vv.w = t*t;
            }
            if (EPI == 3) {
                float4 old = *(const float4*)(crow + jj);
                vv.x += old.x; vv.y += old.y; vv.z += old.z; vv.w += old.w;
            } else if (EPI == 4) {
                float4 old = *(const float4*)(crow + jj);
                float4 g4  = *(const float4*)(grow + jj);
                vv.x = old.x + g4.x*vv.x; vv.y = old.y + g4.y*vv.y;
                vv.z = old.z + g4.z*vv.z; vv.w = old.w + g4.w*vv.w;
            }
            *(float4*)(crow + jj) = vv;
        }
    }
}

// ---------------- WKV: 3-phase chunked scan ----------------
// State (a,b,p) represents exact (A,B)=(a*e^p, b*e^p); A'=e^w A + e^k v is linear,
// so per-chunk transitions compose: A_end = e^{cw} A_start + A_chunk.

// Phase 1: per-chunk local states from zero init. gid = ((b*NCHK)+c)*ADIM + a
__global__ void wkv_chunk_state(const float* __restrict__ K, const float* __restrict__ V,
                                const float* __restrict__ tdec,
                                float* __restrict__ sA, float* __restrict__ sB,
                                float* __restrict__ sP)
{
    int gid = blockIdx.x * blockDim.x + threadIdx.x;
    int a = gid & (ADIM-1);
    int c = (gid >> 10) & (NCHK-1);
    int b = gid >> 15;
    float w = -expf(tdec[a]);
    float aa = 0.f, bb = 0.f, pp = NEGINF;
    size_t idx = ((size_t)(b*TSEQ + c*CHLEN)) * ADIM + a;
    #pragma unroll 4
    for (int t = 0; t < CHLEN; t++) {
        float kt = K[idx], vt = V[idx];
        float q2 = fmaxf(pp + w, kt);
        float e1 = expf(pp + w - q2), e2 = expf(kt - q2);
        aa = e1*aa + e2*vt;
        bb = e1*bb + e2;
        pp = q2;
        idx += ADIM;
    }
    sA[gid] = aa; sB[gid] = bb; sP[gid] = pp;
}

// Phase 2: exclusive prefix over chunks (serial, 32 steps, one thread per (b,a))
__global__ void wkv_prefix(const float* __restrict__ sA, const float* __restrict__ sB,
                           const float* __restrict__ sP,
                           float* __restrict__ pA, float* __restrict__ pB,
                           float* __restrict__ pP,
                           const float* __restrict__ tdec)
{
    int gid = blockIdx.x * blockDim.x + threadIdx.x;   // B*ADIM
    int a = gid & (ADIM-1);
    int b = gid >> 10;
    float w  = -expf(tdec[a]);
    float cw = (float)CHLEN * w;
    float a0 = 0.f, b0 = 0.f, p0 = NEGINF;
    #pragma unroll
    for (int c = 0; c < NCHK; c++) {
        int s = (b*NCHK + c)*ADIM + a;
        pA[s] = a0; pB[s] = b0; pP[s] = p0;
        float la = sA[s], lb = sB[s], lp = sP[s];
        float pn = fmaxf(p0 + cw, lp);
        float e1 = expf(p0 + cw - pn), e2 = expf(lp - pn);
        a0 = e1*a0 + e2*la;
        b0 = e1*b0 + e2*lb;
        p0 = pn;
    }
}

// Phase 3: replay chunks with correct prefix state, emit ry = sigmoid(r)*wkv
__global__ void wkv_output(const float* __restrict__ K, const float* __restrict__ V,
                           const float* __restrict__ R,
                           const float* __restrict__ pA, const float* __restrict__ pB,
                           const float* __restrict__ pP,
                           const float* __restrict__ tdec, const float* __restrict__ tfirst,
                           float* __restrict__ RY)
{
    int gid = blockIdx.x * blockDim.x + threadIdx.x;
    int a = gid & (ADIM-1);
    int c = (gid >> 10) & (NCHK-1);
    int b = gid >> 15;
    float w = -expf(tdec[a]);
    float u = tfirst[a];
    float aa = pA[gid], bb = pB[gid], pp = pP[gid];
    size_t idx = ((size_t)(b*TSEQ + c*CHLEN)) * ADIM + a;
    #pragma unroll 4
    for (int t = 0; t < CHLEN; t++) {
        float kt = K[idx], vt = V[idx], rt = R[idx];
        // output with current carry state
        float q  = fmaxf(pp, u + kt);
        float e1 = expf(pp - q), e2 = expf(u + kt - q);
        float out = (e1*aa + e2*vt) / (e1*bb + e2);
        float sg  = 1.f / (1.f + __expf(-rt));
        RY[idx] = out * sg;
        // state update
        float q2 = fmaxf(pp + w, kt);
        float s1 = expf(pp + w - q2), s2 = expf(kt - q2);
        aa = s1*aa + s2*vt;
        bb = s1*bb + s2;
        pp = q2;
        idx += ADIM;
    }
}

// ---------------- driver ----------------
extern "C" void kernel_launch(void* const* d_in, const int* in_sizes, int n_in,
                              void* d_out, int out_size)
{
    (void)in_sizes; (void)n_in; (void)out_size;
    const int*   ids       = (const int*)  d_in[0];
    const float* embed     = (const float*)d_in[1];
    const float* pre_ln_w  = (const float*)d_in[2];
    const float* pre_ln_b  = (const float*)d_in[3];
    const float* post_ln_w = (const float*)d_in[4];
    const float* post_ln_b = (const float*)d_in[5];
    const float* ln1_w     = (const float*)d_in[6];
    const float* ln1_b     = (const float*)d_in[7];
    const float* ln2_w     = (const float*)d_in[8];
    const float* ln2_b     = (const float*)d_in[9];
    const float* amix_k    = (const float*)d_in[10];
    const float* amix_v    = (const float*)d_in[11];
    const float* amix_r    = (const float*)d_in[12];
    const float* att_wk    = (const float*)d_in[13];
    const float* att_wv    = (const float*)d_in[14];
    const float* att_wr    = (const float*)d_in[15];
    const float* att_wo    = (const float*)d_in[16];
    const float* tdec      = (const float*)d_in[17];
    const float* tfirst    = (const float*)d_in[18];
    const float* fmix_k    = (const float*)d_in[19];
    const float* fmix_r    = (const float*)d_in[20];
    const float* ffn_wk    = (const float*)d_in[21];
    const float* ffn_wr    = (const float*)d_in[22];
    const float* ffn_wv    = (const float*)d_in[23];
    float* out = (float*)d_out;

    float *h, *x, *kb, *vb, *rb, *ryb, *kkb, *rrb, *sA, *sB, *sP, *pA, *pB, *pP;
    cudaGetSymbolAddress((void**)&h,   g_h);
    cudaGetSymbolAddress((void**)&x,   g_x);
    cudaGetSymbolAddress((void**)&kb,  g_k);
    cudaGetSymbolAddress((void**)&vb,  g_v);
    cudaGetSymbolAddress((void**)&rb,  g_r);
    cudaGetSymbolAddress((void**)&ryb, g_ry);
    cudaGetSymbolAddress((void**)&kkb, g_kk);
    cudaGetSymbolAddress((void**)&rrb, g_rr);
    cudaGetSymbolAddress((void**)&sA,  g_sA);
    cudaGetSymbolAddress((void**)&sB,  g_sB);
    cudaGetSymbolAddress((void**)&sP,  g_sP);
    cudaGetSymbolAddress((void**)&pA,  g_pA);
    cudaGetSymbolAddress((void**)&pB,  g_pB);
    cudaGetSymbolAddress((void**)&pP,  g_pP);

    const dim3 gA(ADIM/128, MTOK/128);   // N=1024 outputs
    const dim3 gI(IDIM/128, MTOK/128);   // N=4096 outputs
    const int scan_blks  = (BSZ*NCHK*ADIM)/256;
    const int pref_blks  = (BSZ*ADIM)/256;

    embed_ln_kernel<<<MTOK, 256>>>(ids, embed, pre_ln_w, pre_ln_b, h);

    for (int l = 0; l < LNUM; l++) {
        const size_t oH  = (size_t)l * HDIM;
        const size_t oA  = (size_t)l * ADIM;
        const size_t oAH = (size_t)l * ADIM * HDIM;   // att_wk/wv/wr
        const size_t oHA = (size_t)l * HDIM * ADIM;   // att_wo
        const size_t oIH = (size_t)l * IDIM * HDIM;   // ffn_wk
        const size_t oHH = (size_t)l * HDIM * HDIM;   // ffn_wr
        const size_t oHI = (size_t)l * HDIM * IDIM;   // ffn_wv

        // --- attention ---
        ln_kernel<<<MTOK, 256>>>(h, ln1_w + oH, ln1_b + oH, x);
        gemm128<1,0><<<gA, 256>>>(x, att_wk + oAH, amix_k + oH, nullptr, kb, ADIM, HDIM);
        gemm128<1,0><<<gA, 256>>>(x, att_wv + oAH, amix_v + oH, nullptr, vb, ADIM, HDIM);
        gemm128<1,0><<<gA, 256>>>(x, att_wr + oAH, amix_r + oH, nullptr, rb, ADIM, HDIM);
        wkv_chunk_state<<<scan_blks, 256>>>(kb, vb, tdec + oA, sA, sB, sP);
        wkv_prefix<<<pref_blks, 256>>>(sA, sB, sP, pA, pB, pP, tdec + oA);
        wkv_output<<<scan_blks, 256>>>(kb, vb, rb, pA, pB, pP, tdec + oA, tfirst + oA, ryb);
        gemm128<0,3><<<gA, 256>>>(ryb, att_wo + oHA, nullptr, nullptr, h, HDIM, ADIM);

        // --- feed forward ---
        ln_kernel<<<MTOK, 256>>>(h, ln2_w + oH, ln2_b + oH, x);
        gemm128<1,2><<<gI, 256>>>(x, ffn_wk + oIH, fmix_k + oH, nullptr, kkb, IDIM, HDIM);
        gemm128<1,1><<<gA, 256>>>(x, ffn_wr + oHH, fmix_r + oH, nullptr, rrb, HDIM, HDIM);
        gemm128<0,4><<<gA, 256>>>(kkb, ffn_wv + oHI, nullptr, rrb, h, HDIM, IDIM);
    }

    ln_kernel<<<MTOK, 256>>>(h, post_ln_w, post_ln_b, out);
}

// round 13
// speedup vs baseline: 2.9152x; 2.9152x over previous
#include <cuda_runtime.h>
#include <cuda_bf16.h>
#include <cstdint>

// ---------------- problem constants ----------------
#define LNUM 6
#define HDIM 1024
#define ADIM 1024
#define IDIM 4096
#define BSZ  4
#define TSEQ 2048
#define MTOK (BSZ*TSEQ)          // 8192 tokens
#define NCHK 32                  // WKV chunks per sequence
#define CHLEN (TSEQ/NCHK)        // 64
#define NEGINF (-1e38f)

// ---------------- GEMM tiling (bf16 3-term mma.sync m16n8k16) ----------------
#define BM 128
#define BN 256
#define BK 32
// smem: bf16 rows of 32 elems (64B data) padded to 80B -> word-bank stride 20 (conflict-free)
#define SRB   80                         // bytes per smem row
#define APL   (BM*SRB)                   // 10240 B per A plane
#define BPL   (BN*SRB)                   // 20480 B per B plane
#define STAGEB (2*APL + 2*BPL)           // 61440 B per stage (Ah, Al, Bh, Bl)
#define SMEMSZ (2*STAGEB)                // 122880 B

// ---------------- scratch (static device arrays; no allocations) ----------------
__device__ __align__(128) float g_h [(size_t)MTOK*HDIM];
__device__ __align__(128) float g_x [(size_t)MTOK*HDIM];
__device__ __align__(128) float g_k [(size_t)MTOK*ADIM];
__device__ __align__(128) float g_v [(size_t)MTOK*ADIM];
__device__ __align__(128) float g_r [(size_t)MTOK*ADIM];
__device__ __align__(128) float g_rr[(size_t)MTOK*HDIM];
__device__ __align__(128) float g_sA[BSZ*NCHK*ADIM];
__device__ __align__(128) float g_sB[BSZ*NCHK*ADIM];
__device__ __align__(128) float g_sP[BSZ*NCHK*ADIM];
__device__ __align__(128) float g_pA[BSZ*NCHK*ADIM];
__device__ __align__(128) float g_pB[BSZ*NCHK*ADIM];
__device__ __align__(128) float g_pP[BSZ*NCHK*ADIM];
// bf16 hi/lo planes
__device__ __align__(128) __nv_bfloat16 g_xkh[(size_t)MTOK*HDIM], g_xkl[(size_t)MTOK*HDIM];
__device__ __align__(128) __nv_bfloat16 g_xvh[(size_t)MTOK*HDIM], g_xvl[(size_t)MTOK*HDIM];
__device__ __align__(128) __nv_bfloat16 g_xrh[(size_t)MTOK*HDIM], g_xrl[(size_t)MTOK*HDIM];
__device__ __align__(128) __nv_bfloat16 g_xfh[(size_t)MTOK*HDIM], g_xfl[(size_t)MTOK*HDIM];
__device__ __align__(128) __nv_bfloat16 g_xgh[(size_t)MTOK*HDIM], g_xgl[(size_t)MTOK*HDIM];
__device__ __align__(128) __nv_bfloat16 g_ryh[(size_t)MTOK*ADIM], g_ryl[(size_t)MTOK*ADIM];
__device__ __align__(128) __nv_bfloat16 g_kkh[(size_t)MTOK*IDIM], g_kkl[(size_t)MTOK*IDIM];
__device__ __align__(128) __nv_bfloat16 g_wh [(size_t)IDIM*HDIM], g_wl [(size_t)IDIM*HDIM];

// ---------------- PTX helpers ----------------
__device__ __forceinline__ uint32_t smem_to_u32(const void* p) {
    uint32_t a;
    asm("{ .reg .u64 t; cvta.to.shared.u64 t, %1; cvt.u32.u64 %0, t; }" : "=r"(a) : "l"(p));
    return a;
}
__device__ __forceinline__ void cp_async16(uint32_t dst, const void* src) {
    asm volatile("cp.async.cg.shared.global [%0], [%1], 16;" :: "r"(dst), "l"(src));
}
#define CP_COMMIT() asm volatile("cp.async.commit_group;" ::: "memory")
#define CP_WAIT1()  asm volatile("cp.async.wait_group 1;" ::: "memory")
#define CP_WAIT0()  asm volatile("cp.async.wait_group 0;" ::: "memory")

// bf16 m16n8k16 mma, fp32 accum
__device__ __forceinline__ void mma_bf16(float* c, const uint32_t* a, const uint32_t* b) {
    asm volatile(
        "mma.sync.aligned.m16n8k16.row.col.f32.bf16.bf16.f32 "
        "{%0,%1,%2,%3}, {%4,%5,%6,%7}, {%8,%9}, {%0,%1,%2,%3};"
        : "+f"(c[0]), "+f"(c[1]), "+f"(c[2]), "+f"(c[3])
        : "r"(a[0]), "r"(a[1]), "r"(a[2]), "r"(a[3]), "r"(b[0]), "r"(b[1]));
}

__device__ __forceinline__ void split2(float v0, float v1,
                                       __nv_bfloat162& hv, __nv_bfloat162& lv) {
    __nv_bfloat16 h0 = __float2bfloat16(v0);
    __nv_bfloat16 h1 = __float2bfloat16(v1);
    hv.x = h0; hv.y = h1;
    lv.x = __float2bfloat16(v0 - __bfloat162float(h0));
    lv.y = __float2bfloat16(v1 - __bfloat162float(h1));
}

// ---------------- fp32 -> bf16 hi/lo split (weights) ----------------
__global__ void split_bf16(const float* __restrict__ src,
                           __nv_bfloat16* __restrict__ hi,
                           __nv_bfloat16* __restrict__ lo, int n4)
{
    int i = blockIdx.x * blockDim.x + threadIdx.x;
    if (i >= n4) return;
    float4 v = *(const float4*)(src + (size_t)i * 4);
    __nv_bfloat162 h0, l0, h1, l1;
    split2(v.x, v.y, h0, l0);
    split2(v.z, v.w, h1, l1);
    __nv_bfloat162* hp = (__nv_bfloat162*)(hi + (size_t)i * 4);
    __nv_bfloat162* lp = (__nv_bfloat162*)(lo + (size_t)i * 4);
    hp[0] = h0; hp[1] = h1;
    lp[0] = l0; lp[1] = l1;
}

// ---------------- bf16 3-term tensor GEMM ----------------
// C[M, Nld](+)= epi( A[M,K] @ W[Nld,K]^T ), tile 128x256, K-chunk 32.
// A = Ah + Al, W = Wh + Wl (bf16 planes);  acc = ah*bh + ah*bl + al*bh  (fp32)
// EPI: 0=store fp32, 1=sigmoid fp32, 2=relu^2 -> bf16 hi/lo, 3=C+=acc, 4=C+=gate*acc
template<int EPI>
__global__ __launch_bounds__(256, 1) void mma_gemm(
    const __nv_bfloat16* __restrict__ Ah, const __nv_bfloat16* __restrict__ Al,
    const __nv_bfloat16* __restrict__ Wh, const __nv_bfloat16* __restrict__ Wl,
    const float* __restrict__ gate, float* __restrict__ C,
    __nv_bfloat16* __restrict__ Ch, __nv_bfloat16* __restrict__ Cl,
    int Nld, int K)
{
    extern __shared__ __align__(16) char smem[];
    const uint32_t sbase = smem_to_u32(smem);
    const int tid  = threadIdx.x;
    const int wid  = tid >> 5;
    const int lane = tid & 31;
    const int wm   = wid & 1;            // 2 warps in M
    const int wn   = wid >> 1;           // 4 warps in N
    const int bm   = blockIdx.y * BM;
    const int bn   = blockIdx.x * BN;
    const int r    = lane >> 2;          // 0..7
    const int cq   = lane & 3;           // 0..3

    const __nv_bfloat16* Ahb = Ah + (size_t)bm * K;
    const __nv_bfloat16* Alb = Al + (size_t)bm * K;
    const __nv_bfloat16* Whb = Wh + (size_t)bn * K;
    const __nv_bfloat16* Wlb = Wl + (size_t)bn * K;

    auto load_chunk = [&](int c, int s) {
        uint32_t ah = sbase + (uint32_t)(s * STAGEB);
        uint32_t al = ah + APL;
        uint32_t bh = ah + 2*APL;
        uint32_t bl = bh + BPL;
        const int koff = c * BK;
        #pragma unroll
        for (int i = 0; i < 2; i++) {            // A: 128 rows x 4 granules
            int e = tid + i * 256;
            int row = e >> 2, g = e & 3;
            uint32_t off = (uint32_t)(row * SRB + g * 16);
            size_t src = (size_t)row * K + koff + g * 8;
            cp_async16(ah + off, Ahb + src);
            cp_async16(al + off, Alb + src);
        }
        #pragma unroll
        for (int i = 0; i < 4; i++) {            // B: 256 rows x 4 granules
            int e = tid + i * 256;
            int row = e >> 2, g = e & 3;
            uint32_t off = (uint32_t)(row * SRB + g * 16);
            size_t src = (size_t)row * K + koff + g * 8;
            cp_async16(bh + off, Whb + src);
            cp_async16(bl + off, Wlb + src);
        }
        CP_COMMIT();
    };

    float acc[4][8][4];
    #pragma unroll
    for (int mt = 0; mt < 4; mt++)
        #pragma unroll
        for (int nt = 0; nt < 8; nt++)
            #pragma unroll
            for (int j = 0; j < 4; j++) acc[mt][nt][j] = 0.f;

    const int NC = K / BK;
    load_chunk(0, 0);
    load_chunk(1, 1);

    #pragma unroll 1
    for (int c = 0; c < NC; c++) {
        const int s = c & 1;
        if (c + 1 < NC) { CP_WAIT1(); } else { CP_WAIT0(); }
        __syncthreads();

        const char* sa = smem + s * STAGEB;
        #pragma unroll
        for (int ks = 0; ks < 2; ks++) {
            // A fragments (hi + lo)
            uint32_t ahf[4][4], alf[4][4];
            #pragma unroll
            for (int mt = 0; mt < 4; mt++) {
                const char* p = sa + (wm*64 + mt*16 + r) * SRB + ks*32 + cq*4;
                ahf[mt][0] = *(const uint32_t*)(p);
                ahf[mt][1] = *(const uint32_t*)(p + 8*SRB);
                ahf[mt][2] = *(const uint32_t*)(p + 16);
                ahf[mt][3] = *(const uint32_t*)(p + 8*SRB + 16);
                alf[mt][0] = *(const uint32_t*)(p + APL);
                alf[mt][1] = *(const uint32_t*)(p + APL + 8*SRB);
                alf[mt][2] = *(const uint32_t*)(p + APL + 16);
                alf[mt][3] = *(const uint32_t*)(p + APL + 8*SRB + 16);
            }
            #pragma unroll
            for (int nh = 0; nh < 2; nh++) {
                uint32_t bhf[4][2], blf[4][2];
                #pragma unroll
                for (int q = 0; q < 4; q++) {
                    int nt = nh*4 + q;
                    const char* p = sa + 2*APL + (wn*64 + nt*8 + r) * SRB + ks*32 + cq*4;
                    bhf[q][0] = *(const uint32_t*)(p);
                    bhf[q][1] = *(const uint32_t*)(p + 16);
                    blf[q][0] = *(const uint32_t*)(p + BPL);
                    blf[q][1] = *(const uint32_t*)(p + BPL + 16);
                }
                // term passes: hh, hl, lh (16 independent MMAs per pass)
                #pragma unroll
                for (int mt = 0; mt < 4; mt++)
                    #pragma unroll
                    for (int q = 0; q < 4; q++)
                        mma_bf16(acc[mt][nh*4+q], ahf[mt], bhf[q]);
                #pragma unroll
                for (int mt = 0; mt < 4; mt++)
                    #pragma unroll
                    for (int q = 0; q < 4; q++)
                        mma_bf16(acc[mt][nh*4+q], ahf[mt], blf[q]);
                #pragma unroll
                for (int mt = 0; mt < 4; mt++)
                    #pragma unroll
                    for (int q = 0; q < 4; q++)
                        mma_bf16(acc[mt][nh*4+q], alf[mt], bhf[q]);
            }
        }
        __syncthreads();
        if (c + 2 < NC) load_chunk(c + 2, s);
    }

    // ---------------- epilogue ----------------
    #pragma unroll
    for (int mt = 0; mt < 4; mt++) {
        #pragma unroll
        for (int half = 0; half < 2; half++) {
            const int row = bm + wm*64 + mt*16 + r + half*8;
            #pragma unroll
            for (int nt = 0; nt < 8; nt++) {
                float v0 = acc[mt][nt][half*2 + 0];
                float v1 = acc[mt][nt][half*2 + 1];
                size_t idx = (size_t)row * Nld + bn + wn*64 + nt*8 + 2*cq;
                if (EPI == 1) {
                    v0 = 1.f / (1.f + __expf(-v0));
                    v1 = 1.f / (1.f + __expf(-v1));
                } else if (EPI == 2) {
                    float t0 = fmaxf(v0, 0.f); v0 = t0 * t0;
                    float t1 = fmaxf(v1, 0.f); v1 = t1 * t1;
                    __nv_bfloat162 hv, lv;
                    split2(v0, v1, hv, lv);
                    *(__nv_bfloat162*)(Ch + idx) = hv;
                    *(__nv_bfloat162*)(Cl + idx) = lv;
                    continue;
                } else if (EPI == 3) {
                    float2 old = *(const float2*)(C + idx);
                    v0 += old.x; v1 += old.y;
                } else if (EPI == 4) {
                    float2 old = *(const float2*)(C + idx);
                    float2 g2  = *(const float2*)(gate + idx);
                    v0 = old.x + g2.x * v0;
                    v1 = old.y + g2.y * v1;
                }
                float2 vv; vv.x = v0; vv.y = v1;
                *(float2*)(C + idx) = vv;
            }
        }
    }
}

// ---------------- layernorm ----------------
__device__ __forceinline__ void ln_row_core(const float* __restrict__ src,
                                            const float* __restrict__ w,
                                            const float* __restrict__ b,
                                            float* __restrict__ dst)
{
    int tid = threadIdx.x;
    float4 xv = *(const float4*)(src + tid*4);
    float s = xv.x + xv.y + xv.z + xv.w;
    float q = xv.x*xv.x + xv.y*xv.y + xv.z*xv.z + xv.w*xv.w;
    #pragma unroll
    for (int o = 16; o > 0; o >>= 1) {
        s += __shfl_xor_sync(0xffffffffu, s, o);
        q += __shfl_xor_sync(0xffffffffu, q, o);
    }
    __shared__ float sh_s[8], sh_q[8];
    int wid = tid >> 5;
    if ((tid & 31) == 0) { sh_s[wid] = s; sh_q[wid] = q; }
    __syncthreads();
    float S = 0.f, Q = 0.f;
    #pragma unroll
    for (int i = 0; i < 8; i++) { S += sh_s[i]; Q += sh_q[i]; }
    float mu   = S * (1.0f/HDIM);
    float var  = Q * (1.0f/HDIM) - mu*mu;
    float rstd = rsqrtf(var + 1e-5f);
    float4 wv = *(const float4*)(w + tid*4);
    float4 bv = *(const float4*)(b + tid*4);
    float4 y;
    y.x = (xv.x - mu) * rstd * wv.x + bv.x;
    y.y = (xv.y - mu) * rstd * wv.y + bv.y;
    y.z = (xv.z - mu) * rstd * wv.z + bv.z;
    y.w = (xv.w - mu) * rstd * wv.w + bv.w;
    *(float4*)(dst + tid*4) = y;
}

__global__ void embed_ln_kernel(const int* __restrict__ ids,
                                const float* __restrict__ emb,
                                const float* __restrict__ w,
                                const float* __restrict__ b,
                                float* __restrict__ out)
{
    int row = blockIdx.x;
    int id  = ids[row];
    ln_row_core(emb + (size_t)id*HDIM, w, b, out + (size_t)row*HDIM);
}

__global__ void ln_kernel(const float* __restrict__ src,
                          const float* __restrict__ w,
                          const float* __restrict__ b,
                          float* __restrict__ dst)
{
    int row = blockIdx.x;
    ln_row_core(src + (size_t)row*HDIM, w, b, dst + (size_t)row*HDIM);
}

// ---------------- token-shift mixing -> bf16 hi/lo planes ----------------
__device__ __forceinline__ void mix_store(float4 xc, float4 xp, const float* mp, int t4,
                                          __nv_bfloat16* oh, __nv_bfloat16* ol, size_t base)
{
    float4 m = *(const float4*)(mp + t4);
    float o0 = m.x*xc.x + (1.f-m.x)*xp.x;
    float o1 = m.y*xc.y + (1.f-m.y)*xp.y;
    float o2 = m.z*xc.z + (1.f-m.z)*xp.z;
    float o3 = m.w*xc.w + (1.f-m.w)*xp.w;
    __nv_bfloat162 h0, l0, h1, l1;
    split2(o0, o1, h0, l0);
    split2(o2, o3, h1, l1);
    __nv_bfloat162* hp = (__nv_bfloat162*)(oh + base);
    __nv_bfloat162* lp = (__nv_bfloat162*)(ol + base);
    hp[0] = h0; hp[1] = h1;
    lp[0] = l0; lp[1] = l1;
}

__global__ void mix3_kernel(const float* __restrict__ x,
                            const float* __restrict__ mk, const float* __restrict__ mv,
                            const float* __restrict__ mr,
                            __nv_bfloat16* okh, __nv_bfloat16* okl,
                            __nv_bfloat16* ovh, __nv_bfloat16* ovl,
                            __nv_bfloat16* orh, __nv_bfloat16* orl)
{
    int row = blockIdx.x;
    int t4  = threadIdx.x * 4;
    size_t base = (size_t)row * HDIM + t4;
    float4 xc = *(const float4*)(x + base);
    float4 xp = make_float4(0.f, 0.f, 0.f, 0.f);
    if (row % TSEQ) xp = *(const float4*)(x + base - HDIM);
    mix_store(xc, xp, mk, t4, okh, okl, base);
    mix_store(xc, xp, mv, t4, ovh, ovl, base);
    mix_store(xc, xp, mr, t4, orh, orl, base);
}

__global__ void mix2_kernel(const float* __restrict__ x,
                            const float* __restrict__ mk, const float* __restrict__ mr,
                            __nv_bfloat16* okh, __nv_bfloat16* okl,
                            __nv_bfloat16* orh, __nv_bfloat16* orl)
{
    int row = blockIdx.x;
    int t4  = threadIdx.x * 4;
    size_t base = (size_t)row * HDIM + t4;
    float4 xc = *(const float4*)(x + base);
    float4 xp = make_float4(0.f, 0.f, 0.f, 0.f);
    if (row % TSEQ) xp = *(const float4*)(x + base - HDIM);
    mix_store(xc, xp, mk, t4, okh, okl, base);
    mix_store(xc, xp, mr, t4, orh, orl, base);
}

// ---------------- WKV: 3-phase chunked scan ----------------
__global__ void wkv_chunk_state(const float* __restrict__ K, const float* __restrict__ V,
                                const float* __restrict__ tdec,
                                float* __restrict__ sA, float* __restrict__ sB,
                                float* __restrict__ sP)
{
    int gid = blockIdx.x * blockDim.x + threadIdx.x;
    int a = gid & (ADIM-1);
    int c = (gid >> 10) & (NCHK-1);
    int b = gid >> 15;
    float w = -expf(tdec[a]);
    float aa = 0.f, bb = 0.f, pp = NEGINF;
    size_t idx = ((size_t)(b*TSEQ + c*CHLEN)) * ADIM + a;
    #pragma unroll 4
    for (int t = 0; t < CHLEN; t++) {
        float kt = K[idx], vt = V[idx];
        float d  = pp + w - kt;
        float e  = expf(-fabsf(d));
        float e1 = (d >= 0.f) ? 1.f : e;
        float e2 = (d >= 0.f) ? e : 1.f;
        aa = e1*aa + e2*vt;
        bb = e1*bb + e2;
        pp = fmaxf(pp + w, kt);
        idx += ADIM;
    }
    sA[gid] = aa; sB[gid] = bb; sP[gid] = pp;
}

__global__ void wkv_prefix(const float* __restrict__ sA, const float* __restrict__ sB,
                           const float* __restrict__ sP,
                           float* __restrict__ pA, float* __restrict__ pB,
                           float* __restrict__ pP,
                           const float* __restrict__ tdec)
{
    int gid = blockIdx.x * blockDim.x + threadIdx.x;   // B*ADIM
    int a = gid & (ADIM-1);
    int b = gid >> 10;
    float w  = -expf(tdec[a]);
    float cw = (float)CHLEN * w;
    float a0 = 0.f, b0 = 0.f, p0 = NEGINF;
    #pragma unroll
    for (int c = 0; c < NCHK; c++) {
        int s = (b*NCHK + c)*ADIM + a;
        pA[s] = a0; pB[s] = b0; pP[s] = p0;
        float la = sA[s], lb = sB[s], lp = sP[s];
        float d  = p0 + cw - lp;
        float e  = expf(-fabsf(d));
        float e1 = (d >= 0.f) ? 1.f : e;
        float e2 = (d >= 0.f) ? e : 1.f;
        a0 = e1*a0 + e2*la;
        b0 = e1*b0 + e2*lb;
        p0 = fmaxf(p0 + cw, lp);
    }
}

__global__ void wkv_output(const float* __restrict__ K, const float* __restrict__ V,
                           const float* __restrict__ R,
                           const float* __restrict__ pA, const float* __restrict__ pB,
                           const float* __restrict__ pP,
                           const float* __restrict__ tdec, const float* __restrict__ tfirst,
                           __nv_bfloat16* __restrict__ RYh, __nv_bfloat16* __restrict__ RYl)
{
    int gid = blockIdx.x * blockDim.x + threadIdx.x;
    int a = gid & (ADIM-1);
    int c = (gid >> 10) & (NCHK-1);
    int b = gid >> 15;
    float w = -expf(tdec[a]);
    float u = tfirst[a];
    float aa = pA[gid], bb = pB[gid], pp = pP[gid];
    size_t idx = ((size_t)(b*TSEQ + c*CHLEN)) * ADIM + a;
    #pragma unroll 4
    for (int t = 0; t < CHLEN; t++) {
        float kt = K[idx], vt = V[idx], rt = R[idx];
        float dq = pp - (u + kt);
        float eq = expf(-fabsf(dq));
        float e1 = (dq >= 0.f) ? 1.f : eq;
        float e2 = (dq >= 0.f) ? eq : 1.f;
        float out = (e1*aa + e2*vt) / (e1*bb + e2);
        float sg  = 1.f / (1.f + __expf(-rt));
        float ry  = out * sg;
        __nv_bfloat16 hh = __float2bfloat16(ry);
        RYh[idx] = hh;
        RYl[idx] = __float2bfloat16(ry - __bfloat162float(hh));
        float d  = pp + w - kt;
        float e  = expf(-fabsf(d));
        float s1 = (d >= 0.f) ? 1.f : e;
        float s2 = (d >= 0.f) ? e : 1.f;
        aa = s1*aa + s2*vt;
        bb = s1*bb + s2;
        pp = fmaxf(pp + w, kt);
        idx += ADIM;
    }
}

// ---------------- driver ----------------
extern "C" void kernel_launch(void* const* d_in, const int* in_sizes, int n_in,
                              void* d_out, int out_size)
{
    (void)in_sizes; (void)n_in; (void)out_size;
    const int*   ids       = (const int*)  d_in[0];
    const float* embed     = (const float*)d_in[1];
    const float* pre_ln_w  = (const float*)d_in[2];
    const float* pre_ln_b  = (const float*)d_in[3];
    const float* post_ln_w = (const float*)d_in[4];
    const float* post_ln_b = (const float*)d_in[5];
    const float* ln1_w     = (const float*)d_in[6];
    const float* ln1_b     = (const float*)d_in[7];
    const float* ln2_w     = (const float*)d_in[8];
    const float* ln2_b     = (const float*)d_in[9];
    const float* amix_k    = (const float*)d_in[10];
    const float* amix_v    = (const float*)d_in[11];
    const float* amix_r    = (const float*)d_in[12];
    const float* att_wk    = (const float*)d_in[13];
    const float* att_wv    = (const float*)d_in[14];
    const float* att_wr    = (const float*)d_in[15];
    const float* att_wo    = (const float*)d_in[16];
    const float* tdec      = (const float*)d_in[17];
    const float* tfirst    = (const float*)d_in[18];
    const float* fmix_k    = (const float*)d_in[19];
    const float* fmix_r    = (const float*)d_in[20];
    const float* ffn_wk    = (const float*)d_in[21];
    const float* ffn_wr    = (const float*)d_in[22];
    const float* ffn_wv    = (const float*)d_in[23];
    float* out = (float*)d_out;

    float *h, *x, *kb, *vb, *rb, *rrb, *sA, *sB, *sP, *pA, *pB, *pP;
    __nv_bfloat16 *xkh,*xkl,*xvh,*xvl,*xrh,*xrl,*xfh,*xfl,*xgh,*xgl,*ryh,*ryl,*kkh,*kkl,*wh,*wl;
    cudaGetSymbolAddress((void**)&h,   g_h);
    cudaGetSymbolAddress((void**)&x,   g_x);
    cudaGetSymbolAddress((void**)&kb,  g_k);
    cudaGetSymbolAddress((void**)&vb,  g_v);
    cudaGetSymbolAddress((void**)&rb,  g_r);
    cudaGetSymbolAddress((void**)&rrb, g_rr);
    cudaGetSymbolAddress((void**)&sA,  g_sA);
    cudaGetSymbolAddress((void**)&sB,  g_sB);
    cudaGetSymbolAddress((void**)&sP,  g_sP);
    cudaGetSymbolAddress((void**)&pA,  g_pA);
    cudaGetSymbolAddress((void**)&pB,  g_pB);
    cudaGetSymbolAddress((void**)&pP,  g_pP);
    cudaGetSymbolAddress((void**)&xkh, g_xkh); cudaGetSymbolAddress((void**)&xkl, g_xkl);
    cudaGetSymbolAddress((void**)&xvh, g_xvh); cudaGetSymbolAddress((void**)&xvl, g_xvl);
    cudaGetSymbolAddress((void**)&xrh, g_xrh); cudaGetSymbolAddress((void**)&xrl, g_xrl);
    cudaGetSymbolAddress((void**)&xfh, g_xfh); cudaGetSymbolAddress((void**)&xfl, g_xfl);
    cudaGetSymbolAddress((void**)&xgh, g_xgh); cudaGetSymbolAddress((void**)&xgl, g_xgl);
    cudaGetSymbolAddress((void**)&ryh, g_ryh); cudaGetSymbolAddress((void**)&ryl, g_ryl);
    cudaGetSymbolAddress((void**)&kkh, g_kkh); cudaGetSymbolAddress((void**)&kkl, g_kkl);
    cudaGetSymbolAddress((void**)&wh,  g_wh);  cudaGetSymbolAddress((void**)&wl,  g_wl);

    cudaFuncSetAttribute(mma_gemm<0>, cudaFuncAttributeMaxDynamicSharedMemorySize, SMEMSZ);
    cudaFuncSetAttribute(mma_gemm<1>, cudaFuncAttributeMaxDynamicSharedMemorySize, SMEMSZ);
    cudaFuncSetAttribute(mma_gemm<2>, cudaFuncAttributeMaxDynamicSharedMemorySize, SMEMSZ);
    cudaFuncSetAttribute(mma_gemm<3>, cudaFuncAttributeMaxDynamicSharedMemorySize, SMEMSZ);
    cudaFuncSetAttribute(mma_gemm<4>, cudaFuncAttributeMaxDynamicSharedMemorySize, SMEMSZ);

    const dim3 gA(ADIM/BN, MTOK/BM);     // (4, 64)
    const dim3 gI(IDIM/BN, MTOK/BM);     // (16, 64)
    const int scan_blks = (BSZ*NCHK*ADIM)/256;
    const int pref_blks = (BSZ*ADIM)/256;
    const int splitAH = (ADIM*HDIM/4 + 255)/256;    // 1M-elem weights
    const int splitIH = (IDIM*HDIM/4 + 255)/256;    // 4M-elem weights

    embed_ln_kernel<<<MTOK, 256>>>(ids, embed, pre_ln_w, pre_ln_b, h);

    for (int l = 0; l < LNUM; l++) {
        const size_t oH  = (size_t)l * HDIM;
        const size_t oA  = (size_t)l * ADIM;
        const size_t oAH = (size_t)l * ADIM * HDIM;
        const size_t oHA = (size_t)l * HDIM * ADIM;
        const size_t oIH = (size_t)l * IDIM * HDIM;
        const size_t oHH = (size_t)l * HDIM * HDIM;
        const size_t oHI = (size_t)l * HDIM * IDIM;

        // --- attention ---
        ln_kernel<<<MTOK, 256>>>(h, ln1_w + oH, ln1_b + oH, x);
        mix3_kernel<<<MTOK, 256>>>(x, amix_k + oH, amix_v + oH, amix_r + oH,
                                   xkh, xkl, xvh, xvl, xrh, xrl);
        split_bf16<<<splitAH, 256>>>(att_wk + oAH, wh, wl, ADIM*HDIM/4);
        mma_gemm<0><<<gA, 256, SMEMSZ>>>(xkh, xkl, wh, wl, nullptr, kb, nullptr, nullptr, ADIM, HDIM);
        split_bf16<<<splitAH, 256>>>(att_wv + oAH, wh, wl, ADIM*HDIM/4);
        mma_gemm<0><<<gA, 256, SMEMSZ>>>(xvh, xvl, wh, wl, nullptr, vb, nullptr, nullptr, ADIM, HDIM);
        split_bf16<<<splitAH, 256>>>(att_wr + oAH, wh, wl, ADIM*HDIM/4);
        mma_gemm<0><<<gA, 256, SMEMSZ>>>(xrh, xrl, wh, wl, nullptr, rb, nullptr, nullptr, ADIM, HDIM);
        wkv_chunk_state<<<scan_blks, 256>>>(kb, vb, tdec + oA, sA, sB, sP);
        wkv_prefix<<<pref_blks, 256>>>(sA, sB, sP, pA, pB, pP, tdec + oA);
        wkv_output<<<scan_blks, 256>>>(kb, vb, rb, pA, pB, pP, tdec + oA, tfirst + oA, ryh, ryl);
        split_bf16<<<splitAH, 256>>>(att_wo + oHA, wh, wl, HDIM*ADIM/4);
        mma_gemm<3><<<gA, 256, SMEMSZ>>>(ryh, ryl, wh, wl, nullptr, h, nullptr, nullptr, HDIM, ADIM);

        // --- feed forward ---
        ln_kernel<<<MTOK, 256>>>(h, ln2_w + oH, ln2_b + oH, x);
        mix2_kernel<<<MTOK, 256>>>(x, fmix_k + oH, fmix_r + oH, xfh, xfl, xgh, xgl);
        split_bf16<<<splitIH, 256>>>(ffn_wk + oIH, wh, wl, IDIM*HDIM/4);
        mma_gemm<2><<<gI, 256, SMEMSZ>>>(xfh, xfl, wh, wl, nullptr, nullptr, kkh, kkl, IDIM, HDIM);
        split_bf16<<<splitAH, 256>>>(ffn_wr + oHH, wh, wl, HDIM*HDIM/4);
        mma_gemm<1><<<gA, 256, SMEMSZ>>>(xgh, xgl, wh, wl, nullptr, rrb, nullptr, nullptr, HDIM, HDIM);
        split_bf16<<<splitIH, 256>>>(ffn_wv + oHI, wh, wl, HDIM*IDIM/4);
        mma_gemm<4><<<gA, 256, SMEMSZ>>>(kkh, kkl, wh, wl, rrb, h, nullptr, nullptr, HDIM, IDIM);
    }

    ln_kernel<<<MTOK, 256>>>(h, post_ln_w, post_ln_b, out);
}

// round 15
// speedup vs baseline: 2.9841x; 1.0236x over previous
#include <cuda_runtime.h>
#include <cuda_bf16.h>
#include <cstdint>

// ---------------- problem constants ----------------
#define LNUM 6
#define HDIM 1024
#define ADIM 1024
#define IDIM 4096
#define BSZ  4
#define TSEQ 2048
#define MTOK (BSZ*TSEQ)          // 8192 tokens
#define NCHK 32                  // WKV chunks per sequence
#define CHLEN (TSEQ/NCHK)        // 64
#define NEGINF (-1e38f)

// ---------------- GEMM tiling (bf16 3-term mma.sync m16n8k16) ----------------
#define BM 128
#define BN 256
#define BK 32
// smem: bf16 rows of 32 elems (64B data) padded to 80B -> word-bank stride 20 (conflict-free)
#define SRB   80                         // bytes per smem row
#define APL   (BM*SRB)                   // 10240 B per A plane
#define BPL   (BN*SRB)                   // 20480 B per B plane
#define STAGEB (2*APL + 2*BPL)           // 61440 B per stage (Ah, Al, Bh, Bl)
#define NSTAGE 3
#define SMEMSZ (NSTAGE*STAGEB)           // 184320 B

// ---------------- scratch (static device arrays; no allocations) ----------------
__device__ __align__(128) float g_h [(size_t)MTOK*HDIM];
__device__ __align__(128) float g_x [(size_t)MTOK*HDIM];
__device__ __align__(128) float g_k [(size_t)MTOK*ADIM];
__device__ __align__(128) float g_v [(size_t)MTOK*ADIM];
__device__ __align__(128) float g_r [(size_t)MTOK*ADIM];
__device__ __align__(128) float g_rr[(size_t)MTOK*HDIM];
__device__ __align__(128) float g_sA[BSZ*NCHK*ADIM];
__device__ __align__(128) float g_sB[BSZ*NCHK*ADIM];
__device__ __align__(128) float g_sP[BSZ*NCHK*ADIM];
__device__ __align__(128) float g_pA[BSZ*NCHK*ADIM];
__device__ __align__(128) float g_pB[BSZ*NCHK*ADIM];
__device__ __align__(128) float g_pP[BSZ*NCHK*ADIM];
// bf16 hi/lo planes (activations)
__device__ __align__(128) __nv_bfloat16 g_xkh[(size_t)MTOK*HDIM], g_xkl[(size_t)MTOK*HDIM];
__device__ __align__(128) __nv_bfloat16 g_xvh[(size_t)MTOK*HDIM], g_xvl[(size_t)MTOK*HDIM];
__device__ __align__(128) __nv_bfloat16 g_xrh[(size_t)MTOK*HDIM], g_xrl[(size_t)MTOK*HDIM];
__device__ __align__(128) __nv_bfloat16 g_xfh[(size_t)MTOK*HDIM], g_xfl[(size_t)MTOK*HDIM];
__device__ __align__(128) __nv_bfloat16 g_xgh[(size_t)MTOK*HDIM], g_xgl[(size_t)MTOK*HDIM];
__device__ __align__(128) __nv_bfloat16 g_ryh[(size_t)MTOK*ADIM], g_ryl[(size_t)MTOK*ADIM];
__device__ __align__(128) __nv_bfloat16 g_kkh[(size_t)MTOK*IDIM], g_kkl[(size_t)MTOK*IDIM];
// bf16 hi/lo planes (weights): dedicated k/v/r buffers + shared big buffer
__device__ __align__(128) __nv_bfloat16 g_whk[(size_t)ADIM*HDIM], g_wlk[(size_t)ADIM*HDIM];
__device__ __align__(128) __nv_bfloat16 g_whv[(size_t)ADIM*HDIM], g_wlv[(size_t)ADIM*HDIM];
__device__ __align__(128) __nv_bfloat16 g_whr[(size_t)ADIM*HDIM], g_wlr[(size_t)ADIM*HDIM];
__device__ __align__(128) __nv_bfloat16 g_wh [(size_t)IDIM*HDIM], g_wl [(size_t)IDIM*HDIM];

// ---------------- PTX helpers ----------------
__device__ __forceinline__ uint32_t smem_to_u32(const void* p) {
    uint32_t a;
    asm("{ .reg .u64 t; cvta.to.shared.u64 t, %1; cvt.u32.u64 %0, t; }" : "=r"(a) : "l"(p));
    return a;
}
__device__ __forceinline__ void cp_async16(uint32_t dst, const void* src) {
    asm volatile("cp.async.cg.shared.global [%0], [%1], 16;" :: "r"(dst), "l"(src));
}
#define CP_COMMIT() asm volatile("cp.async.commit_group;" ::: "memory")
#define CP_WAIT1()  asm volatile("cp.async.wait_group 1;" ::: "memory")
#define CP_WAIT0()  asm volatile("cp.async.wait_group 0;" ::: "memory")

// bf16 m16n8k16 mma, fp32 accum
__device__ __forceinline__ void mma_bf16(float* c, const uint32_t* a, const uint32_t* b) {
    asm volatile(
        "mma.sync.aligned.m16n8k16.row.col.f32.bf16.bf16.f32 "
        "{%0,%1,%2,%3}, {%4,%5,%6,%7}, {%8,%9}, {%0,%1,%2,%3};"
        : "+f"(c[0]), "+f"(c[1]), "+f"(c[2]), "+f"(c[3])
        : "r"(a[0]), "r"(a[1]), "r"(a[2]), "r"(a[3]), "r"(b[0]), "r"(b[1]));
}

// ldmatrix x4: 4 8x8 b16 tiles; address groups t0-7/t8-15/t16-23/t24-31 -> r0..r3
__device__ __forceinline__ void ldsm_x4(uint32_t* r, uint32_t addr) {
    asm volatile("ldmatrix.sync.aligned.m8n8.x4.shared.b16 {%0,%1,%2,%3}, [%4];"
        : "=r"(r[0]), "=r"(r[1]), "=r"(r[2]), "=r"(r[3]) : "r"(addr));
}

__device__ __forceinline__ void split2(float v0, float v1,
                                       __nv_bfloat162& hv, __nv_bfloat162& lv) {
    __nv_bfloat16 h0 = __float2bfloat16(v0);
    __nv_bfloat16 h1 = __float2bfloat16(v1);
    hv.x = h0; hv.y = h1;
    lv.x = __float2bfloat16(v0 - __bfloat162float(h0));
    lv.y = __float2bfloat16(v1 - __bfloat162float(h1));
}

// ---------------- fp32 -> bf16 hi/lo split (weights) ----------------
__global__ void split_bf16(const float* __restrict__ src,
                           __nv_bfloat16* __restrict__ hi,
                           __nv_bfloat16* __restrict__ lo, int n4)
{
    int i = blockIdx.x * blockDim.x + threadIdx.x;
    if (i >= n4) return;
    float4 v = *(const float4*)(src + (size_t)i * 4);
    __nv_bfloat162 h0, l0, h1, l1;
    split2(v.x, v.y, h0, l0);
    split2(v.z, v.w, h1, l1);
    __nv_bfloat162* hp = (__nv_bfloat162*)(hi + (size_t)i * 4);
    __nv_bfloat162* lp = (__nv_bfloat162*)(lo + (size_t)i * 4);
    hp[0] = h0; hp[1] = h1;
    lp[0] = l0; lp[1] = l1;
}

// ---------------- bf16 3-term tensor GEMM ----------------
// C[M, Nld](+)= epi( A[M,K] @ W[Nld,K]^T ), tile 128x256, K-chunk 32, 3-stage cp.async.
// A = Ah + Al, W = Wh + Wl (bf16 planes);  acc = ah*bh + ah*bl + al*bh  (fp32)
// EPI: 0=store fp32, 1=sigmoid fp32, 2=relu^2 -> bf16 hi/lo, 3=C+=acc, 4=C+=gate*acc
template<int EPI>
__global__ __launch_bounds__(256, 1) void mma_gemm(
    const __nv_bfloat16* __restrict__ Ah, const __nv_bfloat16* __restrict__ Al,
    const __nv_bfloat16* __restrict__ Wh, const __nv_bfloat16* __restrict__ Wl,
    const float* __restrict__ gate, float* __restrict__ C,
    __nv_bfloat16* __restrict__ Ch, __nv_bfloat16* __restrict__ Cl,
    int Nld, int K)
{
    extern __shared__ __align__(16) char smem[];
    const uint32_t sbase = smem_to_u32(smem);
    const int tid  = threadIdx.x;
    const int wid  = tid >> 5;
    const int lane = tid & 31;
    const int wm   = wid & 1;            // 2 warps in M
    const int wn   = wid >> 1;           // 4 warps in N
    const int bm   = blockIdx.y * BM;
    const int bn   = blockIdx.x * BN;
    const int r    = lane >> 2;          // 0..7 (epilogue)
    const int cq   = lane & 3;           // 0..3 (epilogue)

    const __nv_bfloat16* Ahb = Ah + (size_t)bm * K;
    const __nv_bfloat16* Alb = Al + (size_t)bm * K;
    const __nv_bfloat16* Whb = Wh + (size_t)bn * K;
    const __nv_bfloat16* Wlb = Wl + (size_t)bn * K;

    auto load_chunk = [&](int c, int s) {
        uint32_t ah = sbase + (uint32_t)(s * STAGEB);
        uint32_t al = ah + APL;
        uint32_t bh = ah + 2*APL;
        uint32_t bl = bh + BPL;
        const int koff = c * BK;
        #pragma unroll
        for (int i = 0; i < 2; i++) {            // A: 128 rows x 4 granules
            int e = tid + i * 256;
            int row = e >> 2, g = e & 3;
            uint32_t off = (uint32_t)(row * SRB + g * 16);
            size_t src = (size_t)row * K + koff + g * 8;
            cp_async16(ah + off, Ahb + src);
            cp_async16(al + off, Alb + src);
        }
        #pragma unroll
        for (int i = 0; i < 4; i++) {            // B: 256 rows x 4 granules
            int e = tid + i * 256;
            int row = e >> 2, g = e & 3;
            uint32_t off = (uint32_t)(row * SRB + g * 16);
            size_t src = (size_t)row * K + koff + g * 8;
            cp_async16(bh + off, Whb + src);
            cp_async16(bl + off, Wlb + src);
        }
        CP_COMMIT();
    };

    float acc[4][8][4];
    #pragma unroll
    for (int mt = 0; mt < 4; mt++)
        #pragma unroll
        for (int nt = 0; nt < 8; nt++)
            #pragma unroll
            for (int j = 0; j < 4; j++) acc[mt][nt][j] = 0.f;

    // ldmatrix lane-offsets (16B-row addressing, conflict-free with SRB=80)
    const uint32_t a_loff = (uint32_t)((lane & 15) * SRB + (lane >> 4) * 16);
    const uint32_t b_loff = (uint32_t)((((lane >> 4) << 3) + (lane & 7)) * SRB
                                       + ((lane >> 3) & 1) * 16);
    const uint32_t a_wbase = (uint32_t)(wm * 64 * SRB);
    const uint32_t b_wbase = (uint32_t)(wn * 64 * SRB);

    const int NC = K / BK;
    load_chunk(0, 0);
    load_chunk(1, 1);

    int s = 0;
    #pragma unroll 1
    for (int c = 0; c < NC; c++) {
        if (c + 1 < NC) { CP_WAIT1(); } else { CP_WAIT0(); }
        __syncthreads();                 // all warps done with stage (c-1)%3; stage s ready
        if (c + 2 < NC) {
            int ls = s + 2; if (ls >= NSTAGE) ls -= NSTAGE;
            load_chunk(c + 2, ls);       // overwrites stage consumed at iter c-1 (safe)
        }

        const uint32_t sa = sbase + (uint32_t)(s * STAGEB);
        #pragma unroll
        for (int ks = 0; ks < 2; ks++) {
            const uint32_t ka = (uint32_t)(ks * 32);
            uint32_t ahf[4][4], alf[4][4];
            #pragma unroll
            for (int mt = 0; mt < 4; mt++) {
                uint32_t ad = sa + a_wbase + (uint32_t)(mt * 16 * SRB) + a_loff + ka;
                ldsm_x4(ahf[mt], ad);
                ldsm_x4(alf[mt], ad + APL);
            }
            #pragma unroll
            for (int nh = 0; nh < 2; nh++) {
                uint32_t bhf[4][2], blf[4][2];
                #pragma unroll
                for (int p = 0; p < 2; p++) {
                    uint32_t bd = sa + 2*APL + b_wbase
                                + (uint32_t)((nh * 32 + p * 16) * SRB) + b_loff + ka;
                    ldsm_x4(&bhf[2*p][0], bd);
                    ldsm_x4(&blf[2*p][0], bd + BPL);
                }
                // term passes: hh, hl, lh (16 independent MMAs per pass)
                #pragma unroll
                for (int mt = 0; mt < 4; mt++)
                    #pragma unroll
                    for (int q = 0; q < 4; q++)
                        mma_bf16(acc[mt][nh*4+q], ahf[mt], bhf[q]);
                #pragma unroll
                for (int mt = 0; mt < 4; mt++)
                    #pragma unroll
                    for (int q = 0; q < 4; q++)
                        mma_bf16(acc[mt][nh*4+q], ahf[mt], blf[q]);
                #pragma unroll
                for (int mt = 0; mt < 4; mt++)
                    #pragma unroll
                    for (int q = 0; q < 4; q++)
                        mma_bf16(acc[mt][nh*4+q], alf[mt], bhf[q]);
            }
        }
        if (++s == NSTAGE) s = 0;
    }

    // ---------------- epilogue ----------------
    #pragma unroll
    for (int mt = 0; mt < 4; mt++) {
        #pragma unroll
        for (int half = 0; half < 2; half++) {
            const int row = bm + wm*64 + mt*16 + r + half*8;
            #pragma unroll
            for (int nt = 0; nt < 8; nt++) {
                float v0 = acc[mt][nt][half*2 + 0];
                float v1 = acc[mt][nt][half*2 + 1];
                size_t idx = (size_t)row * Nld + bn + wn*64 + nt*8 + 2*cq;
                if (EPI == 1) {
                    v0 = 1.f / (1.f + __expf(-v0));
                    v1 = 1.f / (1.f + __expf(-v1));
                } else if (EPI == 2) {
                    float t0 = fmaxf(v0, 0.f); v0 = t0 * t0;
                    float t1 = fmaxf(v1, 0.f); v1 = t1 * t1;
                    __nv_bfloat162 hv, lv;
                    split2(v0, v1, hv, lv);
                    *(__nv_bfloat162*)(Ch + idx) = hv;
                    *(__nv_bfloat162*)(Cl + idx) = lv;
                    continue;
                } else if (EPI == 3) {
                    float2 old = *(const float2*)(C + idx);
                    v0 += old.x; v1 += old.y;
                } else if (EPI == 4) {
                    float2 old = *(const float2*)(C + idx);
                    float2 g2  = *(const float2*)(gate + idx);
                    v0 = old.x + g2.x * v0;
                    v1 = old.y + g2.y * v1;
                }
                float2 vv; vv.x = v0; vv.y = v1;
                *(float2*)(C + idx) = vv;
            }
        }
    }
}

// ---------------- layernorm ----------------
__device__ __forceinline__ void ln_row_core(const float* __restrict__ src,
                                            const float* __restrict__ w,
                                            const float* __restrict__ b,
                                            float* __restrict__ dst)
{
    int tid = threadIdx.x;
    float4 xv = *(const float4*)(src + tid*4);
    float s = xv.x + xv.y + xv.z + xv.w;
    float q = xv.x*xv.x + xv.y*xv.y + xv.z*xv.z + xv.w*xv.w;
    #pragma unroll
    for (int o = 16; o > 0; o >>= 1) {
        s += __shfl_xor_sync(0xffffffffu, s, o);
        q += __shfl_xor_sync(0xffffffffu, q, o);
    }
    __shared__ float sh_s[8], sh_q[8];
    int wid = tid >> 5;
    if ((tid & 31) == 0) { sh_s[wid] = s; sh_q[wid] = q; }
    __syncthreads();
    float S = 0.f, Q = 0.f;
    #pragma unroll
    for (int i = 0; i < 8; i++) { S += sh_s[i]; Q += sh_q[i]; }
    float mu   = S * (1.0f/HDIM);
    float var  = Q * (1.0f/HDIM) - mu*mu;
    float rstd = rsqrtf(var + 1e-5f);
    float4 wv = *(const float4*)(w + tid*4);
    float4 bv = *(const float4*)(b + tid*4);
    float4 y;
    y.x = (xv.x - mu) * rstd * wv.x + bv.x;
    y.y = (xv.y - mu) * rstd * wv.y + bv.y;
    y.z = (xv.z - mu) * rstd * wv.z + bv.z;
    y.w = (xv.w - mu) * rstd * wv.w + bv.w;
    *(float4*)(dst + tid*4) = y;
}

__global__ void embed_ln_kernel(const int* __restrict__ ids,
                                const float* __restrict__ emb,
                                const float* __restrict__ w,
                                const float* __restrict__ b,
                                float* __restrict__ out)
{
    int row = blockIdx.x;
    int id  = ids[row];
    ln_row_core(emb + (size_t)id*HDIM, w, b, out + (size_t)row*HDIM);
}

__global__ void ln_kernel(const float* __restrict__ src,
                          const float* __restrict__ w,
                          const float* __restrict__ b,
                          float* __restrict__ dst)
{
    int row = blockIdx.x;
    ln_row_core(src + (size_t)row*HDIM, w, b, dst + (size_t)row*HDIM);
}

// ---------------- token-shift mixing -> bf16 hi/lo planes ----------------
__device__ __forceinline__ void mix_store(float4 xc, float4 xp, const float* mp, int t4,
                                          __nv_bfloat16* oh, __nv_bfloat16* ol, size_t base)
{
    float4 m = *(const float4*)(mp + t4);
    float o0 = m.x*xc.x + (1.f-m.x)*xp.x;
    float o1 = m.y*xc.y + (1.f-m.y)*xp.y;
    float o2 = m.z*xc.z + (1.f-m.z)*xp.z;
    float o3 = m.w*xc.w + (1.f-m.w)*xp.w;
    __nv_bfloat162 h0, l0, h1, l1;
    split2(o0, o1, h0, l0);
    split2(o2, o3, h1, l1);
    __nv_bfloat162* hp = (__nv_bfloat162*)(oh + base);
    __nv_bfloat162* lp = (__nv_bfloat162*)(ol + base);
    hp[0] = h0; hp[1] = h1;
    lp[0] = l0; lp[1] = l1;
}

__global__ void mix3_kernel(const float* __restrict__ x,
                            const float* __restrict__ mk, const float* __restrict__ mv,
                            const float* __restrict__ mr,
                            __nv_bfloat16* okh, __nv_bfloat16* okl,
                            __nv_bfloat16* ovh, __nv_bfloat16* ovl,
                            __nv_bfloat16* orh, __nv_bfloat16* orl)
{
    int row = blockIdx.x;
    int t4  = threadIdx.x * 4;
    size_t base = (size_t)row * HDIM + t4;
    float4 xc = *(const float4*)(x + base);
    float4 xp = make_float4(0.f, 0.f, 0.f, 0.f);
    if (row % TSEQ) xp = *(const float4*)(x + base - HDIM);
    mix_store(xc, xp, mk, t4, okh, okl, base);
    mix_store(xc, xp, mv, t4, ovh, ovl, base);
    mix_store(xc, xp, mr, t4, orh, orl, base);
}

__global__ void mix2_kernel(const float* __restrict__ x,
                            const float* __restrict__ mk, const float* __restrict__ mr,
                            __nv_bfloat16* okh, __nv_bfloat16* okl,
                            __nv_bfloat16* orh, __nv_bfloat16* orl)
{
    int row = blockIdx.x;
    int t4  = threadIdx.x * 4;
    size_t base = (size_t)row * HDIM + t4;
    float4 xc = *(const float4*)(x + base);
    float4 xp = make_float4(0.f, 0.f, 0.f, 0.f);
    if (row % TSEQ) xp = *(const float4*)(x + base - HDIM);
    mix_store(xc, xp, mk, t4, okh, okl, base);
    mix_store(xc, xp, mr, t4, orh, orl, base);
}

// ---------------- WKV: 3-phase chunked scan ----------------
__global__ void wkv_chunk_state(const float* __restrict__ K, const float* __restrict__ V,
                                const float* __restrict__ tdec,
                                float* __restrict__ sA, float* __restrict__ sB,
                                float* __restrict__ sP)
{
    int gid = blockIdx.x * blockDim.x + threadIdx.x;
    int a = gid & (ADIM-1);
    int c = (gid >> 10) & (NCHK-1);
    int b = gid >> 15;
    float w = -expf(tdec[a]);
    float aa = 0.f, bb = 0.f, pp = NEGINF;
    size_t idx = ((size_t)(b*TSEQ + c*CHLEN)) * ADIM + a;
    #pragma unroll 4
    for (int t = 0; t < CHLEN; t++) {
        float kt = K[idx], vt = V[idx];
        float d  = pp + w - kt;
        float e  = expf(-fabsf(d));
        float e1 = (d >= 0.f) ? 1.f : e;
        float e2 = (d >= 0.f) ? e : 1.f;
        aa = e1*aa + e2*vt;
        bb = e1*bb + e2;
        pp = fmaxf(pp + w, kt);
        idx += ADIM;
    }
    sA[gid] = aa; sB[gid] = bb; sP[gid] = pp;
}

__global__ void wkv_prefix(const float* __restrict__ sA, const float* __restrict__ sB,
                           const float* __restrict__ sP,
                           float* __restrict__ pA, float* __restrict__ pB,
                           float* __restrict__ pP,
                           const float* __restrict__ tdec)
{
    int gid = blockIdx.x * blockDim.x + threadIdx.x;   // B*ADIM
    int a = gid & (ADIM-1);
    int b = gid >> 10;
    float w  = -expf(tdec[a]);
    float cw = (float)CHLEN * w;
    float a0 = 0.f, b0 = 0.f, p0 = NEGINF;
    #pragma unroll
    for (int c = 0; c < NCHK; c++) {
        int s = (b*NCHK + c)*ADIM + a;
        pA[s] = a0; pB[s] = b0; pP[s] = p0;
        float la = sA[s], lb = sB[s], lp = sP[s];
        float d  = p0 + cw - lp;
        float e  = expf(-fabsf(d));
        float e1 = (d >= 0.f) ? 1.f : e;
        float e2 = (d >= 0.f) ? e : 1.f;
        a0 = e1*a0 + e2*la;
        b0 = e1*b0 + e2*lb;
        p0 = fmaxf(p0 + cw, lp);
    }
}

__global__ void wkv_output(const float* __restrict__ K, const float* __restrict__ V,
                           const float* __restrict__ R,
                           const float* __restrict__ pA, const float* __restrict__ pB,
                           const float* __restrict__ pP,
                           const float* __restrict__ tdec, const float* __restrict__ tfirst,
                           __nv_bfloat16* __restrict__ RYh, __nv_bfloat16* __restrict__ RYl)
{
    int gid = blockIdx.x * blockDim.x + threadIdx.x;
    int a = gid & (ADIM-1);
    int c = (gid >> 10) & (NCHK-1);
    int b = gid >> 15;
    float w = -expf(tdec[a]);
    float u = tfirst[a];
    float aa = pA[gid], bb = pB[gid], pp = pP[gid];
    size_t idx = ((size_t)(b*TSEQ + c*CHLEN)) * ADIM + a;
    #pragma unroll 4
    for (int t = 0; t < CHLEN; t++) {
        float kt = K[idx], vt = V[idx], rt = R[idx];
        float dq = pp - (u + kt);
        float eq = expf(-fabsf(dq));
        float e1 = (dq >= 0.f) ? 1.f : eq;
        float e2 = (dq >= 0.f) ? eq : 1.f;
        float out = (e1*aa + e2*vt) / (e1*bb + e2);
        float sg  = 1.f / (1.f + __expf(-rt));
        float ry  = out * sg;
        __nv_bfloat16 hh = __float2bfloat16(ry);
        RYh[idx] = hh;
        RYl[idx] = __float2bfloat16(ry - __bfloat162float(hh));
        float d  = pp + w - kt;
        float e  = expf(-fabsf(d));
        float s1 = (d >= 0.f) ? 1.f : e;
        float s2 = (d >= 0.f) ? e : 1.f;
        aa = s1*aa + s2*vt;
        bb = s1*bb + s2;
        pp = fmaxf(pp + w, kt);
        idx += ADIM;
    }
}

// ---------------- driver ----------------
extern "C" void kernel_launch(void* const* d_in, const int* in_sizes, int n_in,
                              void* d_out, int out_size)
{
    (void)in_sizes; (void)n_in; (void)out_size;
    const int*   ids       = (const int*)  d_in[0];
    const float* embed     = (const float*)d_in[1];
    const float* pre_ln_w  = (const float*)d_in[2];
    const float* pre_ln_b  = (const float*)d_in[3];
    const float* post_ln_w = (const float*)d_in[4];
    const float* post_ln_b = (const float*)d_in[5];
    const float* ln1_w     = (const float*)d_in[6];
    const float* ln1_b     = (const float*)d_in[7];
    const float* ln2_w     = (const float*)d_in[8];
    const float* ln2_b     = (const float*)d_in[9];
    const float* amix_k    = (const float*)d_in[10];
    const float* amix_v    = (const float*)d_in[11];
    const float* amix_r    = (const float*)d_in[12];
    const float* att_wk    = (const float*)d_in[13];
    const float* att_wv    = (const float*)d_in[14];
    const float* att_wr    = (const float*)d_in[15];
    const float* att_wo    = (const float*)d_in[16];
    const float* tdec      = (const float*)d_in[17];
    const float* tfirst    = (const float*)d_in[18];
    const float* fmix_k    = (const float*)d_in[19];
    const float* fmix_r    = (const float*)d_in[20];
    const float* ffn_wk    = (const float*)d_in[21];
    const float* ffn_wr    = (const float*)d_in[22];
    const float* ffn_wv    = (const float*)d_in[23];
    float* out = (float*)d_out;

    float *h, *x, *kb, *vb, *rb, *rrb, *sA, *sB, *sP, *pA, *pB, *pP;
    __nv_bfloat16 *xkh,*xkl,*xvh,*xvl,*xrh,*xrl,*xfh,*xfl,*xgh,*xgl,*ryh,*ryl,*kkh,*kkl;
    __nv_bfloat16 *whk,*wlk,*whv,*wlv,*whr,*wlr,*wh,*wl;
    cudaGetSymbolAddress((void**)&h,   g_h);
    cudaGetSymbolAddress((void**)&x,   g_x);
    cudaGetSymbolAddress((void**)&kb,  g_k);
    cudaGetSymbolAddress((void**)&vb,  g_v);
    cudaGetSymbolAddress((void**)&rb,  g_r);
    cudaGetSymbolAddress((void**)&rrb, g_rr);
    cudaGetSymbolAddress((void**)&sA,  g_sA);
    cudaGetSymbolAddress((void**)&sB,  g_sB);
    cudaGetSymbolAddress((void**)&sP,  g_sP);
    cudaGetSymbolAddress((void**)&pA,  g_pA);
    cudaGetSymbolAddress((void**)&pB,  g_pB);
    cudaGetSymbolAddress((void**)&pP,  g_pP);
    cudaGetSymbolAddress((void**)&xkh, g_xkh); cudaGetSymbolAddress((void**)&xkl, g_xkl);
    cudaGetSymbolAddress((void**)&xvh, g_xvh); cudaGetSymbolAddress((void**)&xvl, g_xvl);
    cudaGetSymbolAddress((void**)&xrh, g_xrh); cudaGetSymbolAddress((void**)&xrl, g_xrl);
    cudaGetSymbolAddress((void**)&xfh, g_xfh); cudaGetSymbolAddress((void**)&xfl, g_xfl);
    cudaGetSymbolAddress((void**)&xgh, g_xgh); cudaGetSymbolAddress((void**)&xgl, g_xgl);
    cudaGetSymbolAddress((void**)&ryh, g_ryh); cudaGetSymbolAddress((void**)&ryl, g_ryl);
    cudaGetSymbolAddress((void**)&kkh, g_kkh); cudaGetSymbolAddress((void**)&kkl, g_kkl);
    cudaGetSymbolAddress((void**)&whk, g_whk); cudaGetSymbolAddress((void**)&wlk, g_wlk);
    cudaGetSymbolAddress((void**)&whv, g_whv); cudaGetSymbolAddress((void**)&wlv, g_wlv);
    cudaGetSymbolAddress((void**)&whr, g_whr); cudaGetSymbolAddress((void**)&wlr, g_wlr);
    cudaGetSymbolAddress((void**)&wh,  g_wh);  cudaGetSymbolAddress((void**)&wl,  g_wl);

    cudaFuncSetAttribute(mma_gemm<0>, cudaFuncAttributeMaxDynamicSharedMemorySize, SMEMSZ);
    cudaFuncSetAttribute(mma_gemm<1>, cudaFuncAttributeMaxDynamicSharedMemorySize, SMEMSZ);
    cudaFuncSetAttribute(mma_gemm<2>, cudaFuncAttributeMaxDynamicSharedMemorySize, SMEMSZ);
    cudaFuncSetAttribute(mma_gemm<3>, cudaFuncAttributeMaxDynamicSharedMemorySize, SMEMSZ);
    cudaFuncSetAttribute(mma_gemm<4>, cudaFuncAttributeMaxDynamicSharedMemorySize, SMEMSZ);

    const dim3 gA(ADIM/BN, MTOK/BM);     // (4, 64)
    const dim3 gI(IDIM/BN, MTOK/BM);     // (16, 64)
    const int scan_blks = (BSZ*NCHK*ADIM)/256;
    const int pref_blks = (BSZ*ADIM)/256;
    const int splitAH = (ADIM*HDIM/4 + 255)/256;    // 1M-elem weights
    const int splitIH = (IDIM*HDIM/4 + 255)/256;    // 4M-elem weights

    embed_ln_kernel<<<MTOK, 256>>>(ids, embed, pre_ln_w, pre_ln_b, h);

    for (int l = 0; l < LNUM; l++) {
        const size_t oH  = (size_t)l * HDIM;
        const size_t oA  = (size_t)l * ADIM;
        const size_t oAH = (size_t)l * ADIM * HDIM;
        const size_t oHA = (size_t)l * HDIM * ADIM;
        const size_t oIH = (size_t)l * IDIM * HDIM;
        const size_t oHH = (size_t)l * HDIM * HDIM;
        const size_t oHI = (size_t)l * HDIM * IDIM;

        // --- attention ---  (splits k/v first so the 6th launch overall is a GEMM -> ncu)
        ln_kernel<<<MTOK, 256>>>(h, ln1_w + oH, ln1_b + oH, x);
        mix3_kernel<<<MTOK, 256>>>(x, amix_k + oH, amix_v + oH, amix_r + oH,
                                   xkh, xkl, xvh, xvl, xrh, xrl);
        split_bf16<<<splitAH, 256>>>(att_wk + oAH, whk, wlk, ADIM*HDIM/4);
        split_bf16<<<splitAH, 256>>>(att_wv + oAH, whv, wlv, ADIM*HDIM/4);
        mma_gemm<0><<<gA, 256, SMEMSZ>>>(xkh, xkl, whk, wlk, nullptr, kb, nullptr, nullptr, ADIM, HDIM);
        split_bf16<<<splitAH, 256>>>(att_wr + oAH, whr, wlr, ADIM*HDIM/4);
        mma_gemm<0><<<gA, 256, SMEMSZ>>>(xvh, xvl, whv, wlv, nullptr, vb, nullptr, nullptr, ADIM, HDIM);
        mma_gemm<0><<<gA, 256, SMEMSZ>>>(xrh, xrl, whr, wlr, nullptr, rb, nullptr, nullptr, ADIM, HDIM);
        wkv_chunk_state<<<scan_blks, 256>>>(kb, vb, tdec + oA, sA, sB, sP);
        wkv_prefix<<<pref_blks, 256>>>(sA, sB, sP, pA, pB, pP, tdec + oA);
        wkv_output<<<scan_blks, 256>>>(kb, vb, rb, pA, pB, pP, tdec + oA, tfirst + oA, ryh, ryl);
        split_bf16<<<splitAH, 256>>>(att_wo + oHA, wh, wl, HDIM*ADIM/4);
        mma_gemm<3><<<gA, 256, SMEMSZ>>>(ryh, ryl, wh, wl, nullptr, h, nullptr, nullptr, HDIM, ADIM);

        // --- feed forward ---
        ln_kernel<<<MTOK, 256>>>(h, ln2_w + oH, ln2_b + oH, x);
        mix2_kernel<<<MTOK, 256>>>(x, fmix_k + oH, fmix_r + oH, xfh, xfl, xgh, xgl);
        split_bf16<<<splitIH, 256>>>(ffn_wk + oIH, wh, wl, IDIM*HDIM/4);
        mma_gemm<2><<<gI, 256, SMEMSZ>>>(xfh, xfl, wh, wl, nullptr, nullptr, kkh, kkl, IDIM, HDIM);
        split_bf16<<<splitAH, 256>>>(ffn_wr + oHH, whk, wlk, HDIM*HDIM/4);
        mma_gemm<1><<<gA, 256, SMEMSZ>>>(xgh, xgl, whk, wlk, nullptr, rrb, nullptr, nullptr, HDIM, HDIM);
        split_bf16<<<splitIH, 256>>>(ffn_wv + oHI, wh, wl, HDIM*IDIM/4);
        mma_gemm<4><<<gA, 256, SMEMSZ>>>(kkh, kkl, wh, wl, rrb, h, nullptr, nullptr, HDIM, IDIM);
    }

    ln_kernel<<<MTOK, 256>>>(h, post_ln_w, post_ln_b, out);
}

// round 16
// speedup vs baseline: 3.0250x; 1.0137x over previous
#include <cuda_runtime.h>
#include <cuda_bf16.h>
#include <cstdint>

// ---------------- problem constants ----------------
#define LNUM 6
#define HDIM 1024
#define ADIM 1024
#define IDIM 4096
#define BSZ  4
#define TSEQ 2048
#define MTOK (BSZ*TSEQ)          // 8192 tokens
#define NCHK 32                  // WKV chunks per sequence
#define CHLEN (TSEQ/NCHK)        // 64
#define NEGINF (-1e38f)

// ---------------- GEMM tiling (bf16 3-term mma.sync m16n8k16) ----------------
#define BM 128
#define BN 256
#define BK 32
// smem: bf16 rows of 32 elems (64B data) padded to 80B -> word-bank stride 20 (conflict-free)
#define SRB   80                         // bytes per smem row
#define APL   (BM*SRB)                   // 10240 B per A plane
#define BPL   (BN*SRB)                   // 20480 B per B plane
#define STAGEB (2*APL + 2*BPL)           // 61440 B per stage (Ah, Al, Bh, Bl)
#define NSTAGE 3
#define SMEMSZ (NSTAGE*STAGEB)           // 184320 B

// ---------------- scratch (static device arrays; no allocations) ----------------
__device__ __align__(128) float g_h [(size_t)MTOK*HDIM];
__device__ __align__(128) float g_k [(size_t)MTOK*ADIM];
__device__ __align__(128) float g_v [(size_t)MTOK*ADIM];
__device__ __align__(128) float g_r [(size_t)MTOK*ADIM];
__device__ __align__(128) float g_rr[(size_t)MTOK*HDIM];
__device__ __align__(128) float g_sA[BSZ*NCHK*ADIM];
__device__ __align__(128) float g_sB[BSZ*NCHK*ADIM];
__device__ __align__(128) float g_sP[BSZ*NCHK*ADIM];
__device__ __align__(128) float g_pA[BSZ*NCHK*ADIM];
__device__ __align__(128) float g_pB[BSZ*NCHK*ADIM];
__device__ __align__(128) float g_pP[BSZ*NCHK*ADIM];
// bf16 hi/lo planes (activations)
__device__ __align__(128) __nv_bfloat16 g_xkh[(size_t)MTOK*HDIM], g_xkl[(size_t)MTOK*HDIM];
__device__ __align__(128) __nv_bfloat16 g_xvh[(size_t)MTOK*HDIM], g_xvl[(size_t)MTOK*HDIM];
__device__ __align__(128) __nv_bfloat16 g_xrh[(size_t)MTOK*HDIM], g_xrl[(size_t)MTOK*HDIM];
__device__ __align__(128) __nv_bfloat16 g_xfh[(size_t)MTOK*HDIM], g_xfl[(size_t)MTOK*HDIM];
__device__ __align__(128) __nv_bfloat16 g_xgh[(size_t)MTOK*HDIM], g_xgl[(size_t)MTOK*HDIM];
__device__ __align__(128) __nv_bfloat16 g_ryh[(size_t)MTOK*ADIM], g_ryl[(size_t)MTOK*ADIM];
__device__ __align__(128) __nv_bfloat16 g_kkh[(size_t)MTOK*IDIM], g_kkl[(size_t)MTOK*IDIM];
// bf16 hi/lo planes (weights): dedicated k/v/r buffers + shared big buffer
__device__ __align__(128) __nv_bfloat16 g_whk[(size_t)ADIM*HDIM], g_wlk[(size_t)ADIM*HDIM];
__device__ __align__(128) __nv_bfloat16 g_whv[(size_t)ADIM*HDIM], g_wlv[(size_t)ADIM*HDIM];
__device__ __align__(128) __nv_bfloat16 g_whr[(size_t)ADIM*HDIM], g_wlr[(size_t)ADIM*HDIM];
__device__ __align__(128) __nv_bfloat16 g_wh [(size_t)IDIM*HDIM], g_wl [(size_t)IDIM*HDIM];

// ---------------- PTX helpers ----------------
__device__ __forceinline__ uint32_t smem_to_u32(const void* p) {
    uint32_t a;
    asm("{ .reg .u64 t; cvta.to.shared.u64 t, %1; cvt.u32.u64 %0, t; }" : "=r"(a) : "l"(p));
    return a;
}
__device__ __forceinline__ void cp_async16(uint32_t dst, const void* src) {
    asm volatile("cp.async.cg.shared.global [%0], [%1], 16;" :: "r"(dst), "l"(src));
}
#define CP_COMMIT() asm volatile("cp.async.commit_group;" ::: "memory")
#define CP_WAIT2()  asm volatile("cp.async.wait_group 2;" ::: "memory")
#define CP_WAIT1()  asm volatile("cp.async.wait_group 1;" ::: "memory")
#define CP_WAIT0()  asm volatile("cp.async.wait_group 0;" ::: "memory")

// bf16 m16n8k16 mma, fp32 accum
__device__ __forceinline__ void mma_bf16(float* c, const uint32_t* a, const uint32_t* b) {
    asm volatile(
        "mma.sync.aligned.m16n8k16.row.col.f32.bf16.bf16.f32 "
        "{%0,%1,%2,%3}, {%4,%5,%6,%7}, {%8,%9}, {%0,%1,%2,%3};"
        : "+f"(c[0]), "+f"(c[1]), "+f"(c[2]), "+f"(c[3])
        : "r"(a[0]), "r"(a[1]), "r"(a[2]), "r"(a[3]), "r"(b[0]), "r"(b[1]));
}

// ldmatrix x4: 4 8x8 b16 tiles; address groups t0-7/t8-15/t16-23/t24-31 -> r0..r3
__device__ __forceinline__ void ldsm_x4(uint32_t* r, uint32_t addr) {
    asm volatile("ldmatrix.sync.aligned.m8n8.x4.shared.b16 {%0,%1,%2,%3}, [%4];"
        : "=r"(r[0]), "=r"(r[1]), "=r"(r[2]), "=r"(r[3]) : "r"(addr));
}

__device__ __forceinline__ void split2(float v0, float v1,
                                       __nv_bfloat162& hv, __nv_bfloat162& lv) {
    __nv_bfloat16 h0 = __float2bfloat16(v0);
    __nv_bfloat16 h1 = __float2bfloat16(v1);
    hv.x = h0; hv.y = h1;
    lv.x = __float2bfloat16(v0 - __bfloat162float(h0));
    lv.y = __float2bfloat16(v1 - __bfloat162float(h1));
}

// ---------------- fp32 -> bf16 hi/lo split (weights) ----------------
__global__ void split_bf16(const float* __restrict__ src,
                           __nv_bfloat16* __restrict__ hi,
                           __nv_bfloat16* __restrict__ lo, int n4)
{
    int i = blockIdx.x * blockDim.x + threadIdx.x;
    if (i >= n4) return;
    float4 v = *(const float4*)(src + (size_t)i * 4);
    __nv_bfloat162 h0, l0, h1, l1;
    split2(v.x, v.y, h0, l0);
    split2(v.z, v.w, h1, l1);
    __nv_bfloat162* hp = (__nv_bfloat162*)(hi + (size_t)i * 4);
    __nv_bfloat162* lp = (__nv_bfloat162*)(lo + (size_t)i * 4);
    hp[0] = h0; hp[1] = h1;
    lp[0] = l0; lp[1] = l1;
}

// ---------------- bf16 3-term tensor GEMM ----------------
// C[M, Nld](+)= epi( A[M,K] @ W[Nld,K]^T ), tile 128x256, K-chunk 32, 3-stage cp.async.
// A = Ah + Al, W = Wh + Wl (bf16 planes);  acc = ah*bh + ah*bl + al*bh  (fp32)
// EPI: 0=store fp32, 1=sigmoid fp32, 2=relu^2 -> bf16 hi/lo, 3=C+=acc, 4=C+=gate*acc
template<int EPI>
__global__ __launch_bounds__(256, 1) void mma_gemm(
    const __nv_bfloat16* __restrict__ Ah, const __nv_bfloat16* __restrict__ Al,
    const __nv_bfloat16* __restrict__ Wh, const __nv_bfloat16* __restrict__ Wl,
    const float* __restrict__ gate, float* __restrict__ C,
    __nv_bfloat16* __restrict__ Ch, __nv_bfloat16* __restrict__ Cl,
    int Nld, int K)
{
    extern __shared__ __align__(16) char smem[];
    const uint32_t sbase = smem_to_u32(smem);
    const int tid  = threadIdx.x;
    const int wid  = tid >> 5;
    const int lane = tid & 31;
    const int wm   = wid & 1;            // 2 warps in M
    const int wn   = wid >> 1;           // 4 warps in N
    const int bm   = blockIdx.y * BM;
    const int bn   = blockIdx.x * BN;
    const int r    = lane >> 2;          // 0..7 (epilogue)
    const int cq   = lane & 3;           // 0..3 (epilogue)

    const __nv_bfloat16* Ahb = Ah + (size_t)bm * K;
    const __nv_bfloat16* Alb = Al + (size_t)bm * K;
    const __nv_bfloat16* Whb = Wh + (size_t)bn * K;
    const __nv_bfloat16* Wlb = Wl + (size_t)bn * K;

    auto load_chunk = [&](int c, int s) {
        uint32_t ah = sbase + (uint32_t)(s * STAGEB);
        uint32_t al = ah + APL;
        uint32_t bh = ah + 2*APL;
        uint32_t bl = bh + BPL;
        const int koff = c * BK;
        #pragma unroll
        for (int i = 0; i < 2; i++) {            // A: 128 rows x 4 granules
            int e = tid + i * 256;
            int row = e >> 2, g = e & 3;
            uint32_t off = (uint32_t)(row * SRB + g * 16);
            size_t src = (size_t)row * K + koff + g * 8;
            cp_async16(ah + off, Ahb + src);
            cp_async16(al + off, Alb + src);
        }
        #pragma unroll
        for (int i = 0; i < 4; i++) {            // B: 256 rows x 4 granules
            int e = tid + i * 256;
            int row = e >> 2, g = e & 3;
            uint32_t off = (uint32_t)(row * SRB + g * 16);
            size_t src = (size_t)row * K + koff + g * 8;
            cp_async16(bh + off, Whb + src);
            cp_async16(bl + off, Wlb + src);
        }
        CP_COMMIT();
    };

    float acc[4][8][4];
    #pragma unroll
    for (int mt = 0; mt < 4; mt++)
        #pragma unroll
        for (int nt = 0; nt < 8; nt++)
            #pragma unroll
            for (int j = 0; j < 4; j++) acc[mt][nt][j] = 0.f;

    // ldmatrix lane-offsets (16B-row addressing, conflict-free with SRB=80)
    const uint32_t a_loff = (uint32_t)((lane & 15) * SRB + (lane >> 4) * 16);
    const uint32_t b_loff = (uint32_t)((((lane >> 4) << 3) + (lane & 7)) * SRB
                                       + ((lane >> 3) & 1) * 16);
    const uint32_t a_wbase = (uint32_t)(wm * 64 * SRB);
    const uint32_t b_wbase = (uint32_t)(wn * 64 * SRB);

    const int NC = K / BK;
    load_chunk(0, 0);
    load_chunk(1, 1);

    int s = 0;
    #pragma unroll 1
    for (int c = 0; c < NC; c++) {
        __syncthreads();                 // all warps done reading stage (c-1)%3
        if (c + 2 < NC) {
            int ls = s + 2; if (ls >= NSTAGE) ls -= NSTAGE;
            load_chunk(c + 2, ls);       // overwrites stage consumed at iter c-1 (safe)
            CP_WAIT2();                  // chunk c resident; chunks c+1, c+2 in flight
        } else if (c + 1 < NC) {
            CP_WAIT1();
        } else {
            CP_WAIT0();
        }

        const uint32_t sa = sbase + (uint32_t)(s * STAGEB);
        #pragma unroll
        for (int ks = 0; ks < 2; ks++) {
            const uint32_t ka = (uint32_t)(ks * 32);
            uint32_t ahf[4][4], alf[4][4];
            #pragma unroll
            for (int mt = 0; mt < 4; mt++) {
                uint32_t ad = sa + a_wbase + (uint32_t)(mt * 16 * SRB) + a_loff + ka;
                ldsm_x4(ahf[mt], ad);
                ldsm_x4(alf[mt], ad + APL);
            }
            #pragma unroll
            for (int nh = 0; nh < 2; nh++) {
                uint32_t bhf[4][2], blf[4][2];
                #pragma unroll
                for (int p = 0; p < 2; p++) {
                    uint32_t bd = sa + 2*APL + b_wbase
                                + (uint32_t)((nh * 32 + p * 16) * SRB) + b_loff + ka;
                    ldsm_x4(&bhf[2*p][0], bd);
                    ldsm_x4(&blf[2*p][0], bd + BPL);
                }
                // term passes: hh, hl, lh (16 independent MMAs per pass)
                #pragma unroll
                for (int mt = 0; mt < 4; mt++)
                    #pragma unroll
                    for (int q = 0; q < 4; q++)
                        mma_bf16(acc[mt][nh*4+q], ahf[mt], bhf[q]);
                #pragma unroll
                for (int mt = 0; mt < 4; mt++)
                    #pragma unroll
                    for (int q = 0; q < 4; q++)
                        mma_bf16(acc[mt][nh*4+q], ahf[mt], blf[q]);
                #pragma unroll
                for (int mt = 0; mt < 4; mt++)
                    #pragma unroll
                    for (int q = 0; q < 4; q++)
                        mma_bf16(acc[mt][nh*4+q], alf[mt], bhf[q]);
            }
        }
        if (++s == NSTAGE) s = 0;
    }

    // ---------------- epilogue ----------------
    #pragma unroll
    for (int mt = 0; mt < 4; mt++) {
        #pragma unroll
        for (int half = 0; half < 2; half++) {
            const int row = bm + wm*64 + mt*16 + r + half*8;
            #pragma unroll
            for (int nt = 0; nt < 8; nt++) {
                float v0 = acc[mt][nt][half*2 + 0];
                float v1 = acc[mt][nt][half*2 + 1];
                size_t idx = (size_t)row * Nld + bn + wn*64 + nt*8 + 2*cq;
                if (EPI == 1) {
                    v0 = 1.f / (1.f + __expf(-v0));
                    v1 = 1.f / (1.f + __expf(-v1));
                } else if (EPI == 2) {
                    float t0 = fmaxf(v0, 0.f); v0 = t0 * t0;
                    float t1 = fmaxf(v1, 0.f); v1 = t1 * t1;
                    __nv_bfloat162 hv, lv;
                    split2(v0, v1, hv, lv);
                    *(__nv_bfloat162*)(Ch + idx) = hv;
                    *(__nv_bfloat162*)(Cl + idx) = lv;
                    continue;
                } else if (EPI == 3) {
                    float2 old = *(const float2*)(C + idx);
                    v0 += old.x; v1 += old.y;
                } else if (EPI == 4) {
                    float2 old = *(const float2*)(C + idx);
                    float2 g2  = *(const float2*)(gate + idx);
                    v0 = old.x + g2.x * v0;
                    v1 = old.y + g2.y * v1;
                }
                float2 vv; vv.x = v0; vv.y = v1;
                *(float2*)(C + idx) = vv;
            }
        }
    }
}

// ---------------- layernorm (post / embed) ----------------
__device__ __forceinline__ void ln_row_core(const float* __restrict__ src,
                                            const float* __restrict__ w,
                                            const float* __restrict__ b,
                                            float* __restrict__ dst)
{
    int tid = threadIdx.x;
    float4 xv = *(const float4*)(src + tid*4);
    float s = xv.x + xv.y + xv.z + xv.w;
    float q = xv.x*xv.x + xv.y*xv.y + xv.z*xv.z + xv.w*xv.w;
    #pragma unroll
    for (int o = 16; o > 0; o >>= 1) {
        s += __shfl_xor_sync(0xffffffffu, s, o);
        q += __shfl_xor_sync(0xffffffffu, q, o);
    }
    __shared__ float sh_s[8], sh_q[8];
    int wid = tid >> 5;
    if ((tid & 31) == 0) { sh_s[wid] = s; sh_q[wid] = q; }
    __syncthreads();
    float S = 0.f, Q = 0.f;
    #pragma unroll
    for (int i = 0; i < 8; i++) { S += sh_s[i]; Q += sh_q[i]; }
    float mu   = S * (1.0f/HDIM);
    float var  = Q * (1.0f/HDIM) - mu*mu;
    float rstd = rsqrtf(var + 1e-5f);
    float4 wv = *(const float4*)(w + tid*4);
    float4 bv = *(const float4*)(b + tid*4);
    float4 y;
    y.x = (xv.x - mu) * rstd * wv.x + bv.x;
    y.y = (xv.y - mu) * rstd * wv.y + bv.y;
    y.z = (xv.z - mu) * rstd * wv.z + bv.z;
    y.w = (xv.w - mu) * rstd * wv.w + bv.w;
    *(float4*)(dst + tid*4) = y;
}

__global__ void embed_ln_kernel(const int* __restrict__ ids,
                                const float* __restrict__ emb,
                                const float* __restrict__ w,
                                const float* __restrict__ b,
                                float* __restrict__ out)
{
    int row = blockIdx.x;
    int id  = ids[row];
    ln_row_core(emb + (size_t)id*HDIM, w, b, out + (size_t)row*HDIM);
}

__global__ void ln_kernel(const float* __restrict__ src,
                          const float* __restrict__ w,
                          const float* __restrict__ b,
                          float* __restrict__ dst)
{
    int row = blockIdx.x;
    ln_row_core(src + (size_t)row*HDIM, w, b, dst + (size_t)row*HDIM);
}

// ---------------- fused LN + token-shift mixing -> bf16 hi/lo planes ----------------
// Each block handles one row: computes LN(row) and LN(row-1) (redundantly, cheap),
// then emits mixed planes  m*ln(x_t) + (1-m)*ln(x_{t-1}).
__device__ __forceinline__ void mix_store(float4 xc, float4 xp, const float* mp, int t4,
                                          __nv_bfloat16* oh, __nv_bfloat16* ol, size_t base)
{
    float4 m = *(const float4*)(mp + t4);
    float o0 = m.x*xc.x + (1.f-m.x)*xp.x;
    float o1 = m.y*xc.y + (1.f-m.y)*xp.y;
    float o2 = m.z*xc.z + (1.f-m.z)*xp.z;
    float o3 = m.w*xc.w + (1.f-m.w)*xp.w;
    __nv_bfloat162 h0, l0, h1, l1;
    split2(o0, o1, h0, l0);
    split2(o2, o3, h1, l1);
    __nv_bfloat162* hp = (__nv_bfloat162*)(oh + base);
    __nv_bfloat162* lp = (__nv_bfloat162*)(ol + base);
    hp[0] = h0; hp[1] = h1;
    lp[0] = l0; lp[1] = l1;
}

// computes LN of cur & prev rows; yp = 0 when no prev (t=0)
__device__ __forceinline__ void ln2_rows(const float* __restrict__ h,
                                         const float* __restrict__ w,
                                         const float* __restrict__ b,
                                         int row, float4& yc, float4& yp, int t4)
{
    const bool hasprev = (row % TSEQ) != 0;
    size_t base = (size_t)row * HDIM + t4;
    float4 xc = *(const float4*)(h + base);
    float4 xq = make_float4(0.f,0.f,0.f,0.f);
    if (hasprev) xq = *(const float4*)(h + base - HDIM);
    float s  = xc.x + xc.y + xc.z + xc.w;
    float q  = xc.x*xc.x + xc.y*xc.y + xc.z*xc.z + xc.w*xc.w;
    float sp = xq.x + xq.y + xq.z + xq.w;
    float qp = xq.x*xq.x + xq.y*xq.y + xq.z*xq.z + xq.w*xq.w;
    #pragma unroll
    for (int o = 16; o > 0; o >>= 1) {
        s  += __shfl_xor_sync(0xffffffffu, s,  o);
        q  += __shfl_xor_sync(0xffffffffu, q,  o);
        sp += __shfl_xor_sync(0xffffffffu, sp, o);
        qp += __shfl_xor_sync(0xffffffffu, qp, o);
    }
    __shared__ float sh[4][8];
    int wid = threadIdx.x >> 5;
    if ((threadIdx.x & 31) == 0) { sh[0][wid]=s; sh[1][wid]=q; sh[2][wid]=sp; sh[3][wid]=qp; }
    __syncthreads();
    float S=0.f, Q=0.f, SP=0.f, QP=0.f;
    #pragma unroll
    for (int i = 0; i < 8; i++) { S+=sh[0][i]; Q+=sh[1][i]; SP+=sh[2][i]; QP+=sh[3][i]; }
    float mu   = S * (1.0f/HDIM);
    float var  = Q * (1.0f/HDIM) - mu*mu;
    float rstd = rsqrtf(var + 1e-5f);
    float mup  = SP * (1.0f/HDIM);
    float varp = QP * (1.0f/HDIM) - mup*mup;
    float rsp  = rsqrtf(varp + 1e-5f);
    float4 wv = *(const float4*)(w + t4);
    float4 bv = *(const float4*)(b + t4);
    yc.x = (xc.x - mu)*rstd*wv.x + bv.x;
    yc.y = (xc.y - mu)*rstd*wv.y + bv.y;
    yc.z = (xc.z - mu)*rstd*wv.z + bv.z;
    yc.w = (xc.w - mu)*rstd*wv.w + bv.w;
    if (hasprev) {
        yp.x = (xq.x - mup)*rsp*wv.x + bv.x;
        yp.y = (xq.y - mup)*rsp*wv.y + bv.y;
        yp.z = (xq.z - mup)*rsp*wv.z + bv.z;
        yp.w = (xq.w - mup)*rsp*wv.w + bv.w;
    } else {
        yp = make_float4(0.f,0.f,0.f,0.f);
    }
}

__global__ void ln_mix3_kernel(const float* __restrict__ h,
                               const float* __restrict__ w, const float* __restrict__ b,
                               const float* __restrict__ mk, const float* __restrict__ mv,
                               const float* __restrict__ mr,
                               __nv_bfloat16* okh, __nv_bfloat16* okl,
                               __nv_bfloat16* ovh, __nv_bfloat16* ovl,
                               __nv_bfloat16* orh, __nv_bfloat16* orl)
{
    int row = blockIdx.x;
    int t4  = threadIdx.x * 4;
    float4 yc, yp;
    ln2_rows(h, w, b, row, yc, yp, t4);
    size_t base = (size_t)row * HDIM + t4;
    mix_store(yc, yp, mk, t4, okh, okl, base);
    mix_store(yc, yp, mv, t4, ovh, ovl, base);
    mix_store(yc, yp, mr, t4, orh, orl, base);
}

__global__ void ln_mix2_kernel(const float* __restrict__ h,
                               const float* __restrict__ w, const float* __restrict__ b,
                               const float* __restrict__ mk, const float* __restrict__ mr,
                               __nv_bfloat16* okh, __nv_bfloat16* okl,
                               __nv_bfloat16* orh, __nv_bfloat16* orl)
{
    int row = blockIdx.x;
    int t4  = threadIdx.x * 4;
    float4 yc, yp;
    ln2_rows(h, w, b, row, yc, yp, t4);
    size_t base = (size_t)row * HDIM + t4;
    mix_store(yc, yp, mk, t4, okh, okl, base);
    mix_store(yc, yp, mr, t4, orh, orl, base);
}

// ---------------- WKV: 3-phase chunked scan ----------------
// exp(min(0,d)) / exp(min(0,-d)) selection via a single __expf(-|d|).
__global__ void wkv_chunk_state(const float* __restrict__ K, const float* __restrict__ V,
                                const float* __restrict__ tdec,
                                float* __restrict__ sA, float* __restrict__ sB,
                                float* __restrict__ sP)
{
    int gid = blockIdx.x * blockDim.x + threadIdx.x;
    int a = gid & (ADIM-1);
    int c = (gid >> 10) & (NCHK-1);
    int b = gid >> 15;
    float w = -__expf(tdec[a]);
    float aa = 0.f, bb = 0.f, pp = NEGINF;
    size_t idx = ((size_t)(b*TSEQ + c*CHLEN)) * ADIM + a;
    #pragma unroll 4
    for (int t = 0; t < CHLEN; t++) {
        float kt = K[idx], vt = V[idx];
        float d  = pp + w - kt;
        float e  = __expf(-fabsf(d));
        float e1 = (d >= 0.f) ? 1.f : e;
        float e2 = (d >= 0.f) ? e : 1.f;
        aa = e1*aa + e2*vt;
        bb = e1*bb + e2;
        pp = fmaxf(pp + w, kt);
        idx += ADIM;
    }
    sA[gid] = aa; sB[gid] = bb; sP[gid] = pp;
}

__global__ void wkv_prefix(const float* __restrict__ sA, const float* __restrict__ sB,
                           const float* __restrict__ sP,
                           float* __restrict__ pA, float* __restrict__ pB,
                           float* __restrict__ pP,
                           const float* __restrict__ tdec)
{
    int gid = blockIdx.x * blockDim.x + threadIdx.x;   // B*ADIM
    int a = gid & (ADIM-1);
    int b = gid >> 10;
    float w  = -__expf(tdec[a]);
    float cw = (float)CHLEN * w;
    float a0 = 0.f, b0 = 0.f, p0 = NEGINF;
    #pragma unroll
    for (int c = 0; c < NCHK; c++) {
        int s = (b*NCHK + c)*ADIM + a;
        pA[s] = a0; pB[s] = b0; pP[s] = p0;
        float la = sA[s], lb = sB[s], lp = sP[s];
        float d  = p0 + cw - lp;
        float e  = __expf(-fabsf(d));
        float e1 = (d >= 0.f) ? 1.f : e;
        float e2 = (d >= 0.f) ? e : 1.f;
        a0 = e1*a0 + e2*la;
        b0 = e1*b0 + e2*lb;
        p0 = fmaxf(p0 + cw, lp);
    }
}

__global__ void wkv_output(const float* __restrict__ K, const float* __restrict__ V,
                           const float* __restrict__ R,
                           const float* __restrict__ pA, const float* __restrict__ pB,
                           const float* __restrict__ pP,
                           const float* __restrict__ tdec, const float* __restrict__ tfirst,
                           __nv_bfloat16* __restrict__ RYh, __nv_bfloat16* __restrict__ RYl)
{
    int gid = blockIdx.x * blockDim.x + threadIdx.x;
    int a = gid & (ADIM-1);
    int c = (gid >> 10) & (NCHK-1);
    int b = gid >> 15;
    float w = -__expf(tdec[a]);
    float u = tfirst[a];
    float aa = pA[gid], bb = pB[gid], pp = pP[gid];
    size_t idx = ((size_t)(b*TSEQ + c*CHLEN)) * ADIM + a;
    #pragma unroll 4
    for (int t = 0; t < CHLEN; t++) {
        float kt = K[idx], vt = V[idx], rt = R[idx];
        float dq = pp - (u + kt);
        float eq = __expf(-fabsf(dq));
        float e1 = (dq >= 0.f) ? 1.f : eq;
        float e2 = (dq >= 0.f) ? eq : 1.f;
        float out = (e1*aa + e2*vt) / (e1*bb + e2);
        float sg  = 1.f / (1.f + __expf(-rt));
        float ry  = out * sg;
        __nv_bfloat16 hh = __float2bfloat16(ry);
        RYh[idx] = hh;
        RYl[idx] = __float2bfloat16(ry - __bfloat162float(hh));
        float d  = pp + w - kt;
        float e  = __expf(-fabsf(d));
        float s1 = (d >= 0.f) ? 1.f : e;
        float s2 = (d >= 0.f) ? e : 1.f;
        aa = s1*aa + s2*vt;
        bb = s1*bb + s2;
        pp = fmaxf(pp + w, kt);
        idx += ADIM;
    }
}

// ---------------- driver ----------------
extern "C" void kernel_launch(void* const* d_in, const int* in_sizes, int n_in,
                              void* d_out, int out_size)
{
    (void)in_sizes; (void)n_in; (void)out_size;
    const int*   ids       = (const int*)  d_in[0];
    const float* embed     = (const float*)d_in[1];
    const float* pre_ln_w  = (const float*)d_in[2];
    const float* pre_ln_b  = (const float*)d_in[3];
    const float* post_ln_w = (const float*)d_in[4];
    const float* post_ln_b = (const float*)d_in[5];
    const float* ln1_w     = (const float*)d_in[6];
    const float* ln1_b     = (const float*)d_in[7];
    const float* ln2_w     = (const float*)d_in[8];
    const float* ln2_b     = (const float*)d_in[9];
    const float* amix_k    = (const float*)d_in[10];
    const float* amix_v    = (const float*)d_in[11];
    const float* amix_r    = (const float*)d_in[12];
    const float* att_wk    = (const float*)d_in[13];
    const float* att_wv    = (const float*)d_in[14];
    const float* att_wr    = (const float*)d_in[15];
    const float* att_wo    = (const float*)d_in[16];
    const float* tdec      = (const float*)d_in[17];
    const float* tfirst    = (const float*)d_in[18];
    const float* fmix_k    = (const float*)d_in[19];
    const float* fmix_r    = (const float*)d_in[20];
    const float* ffn_wk    = (const float*)d_in[21];
    const float* ffn_wr    = (const float*)d_in[22];
    const float* ffn_wv    = (const float*)d_in[23];
    float* out = (float*)d_out;

    float *h, *kb, *vb, *rb, *rrb, *sA, *sB, *sP, *pA, *pB, *pP;
    __nv_bfloat16 *xkh,*xkl,*xvh,*xvl,*xrh,*xrl,*xfh,*xfl,*xgh,*xgl,*ryh,*ryl,*kkh,*kkl;
    __nv_bfloat16 *whk,*wlk,*whv,*wlv,*whr,*wlr,*wh,*wl;
    cudaGetSymbolAddress((void**)&h,   g_h);
    cudaGetSymbolAddress((void**)&kb,  g_k);
    cudaGetSymbolAddress((void**)&vb,  g_v);
    cudaGetSymbolAddress((void**)&rb,  g_r);
    cudaGetSymbolAddress((void**)&rrb, g_rr);
    cudaGetSymbolAddress((void**)&sA,  g_sA);
    cudaGetSymbolAddress((void**)&sB,  g_sB);
    cudaGetSymbolAddress((void**)&sP,  g_sP);
    cudaGetSymbolAddress((void**)&pA,  g_pA);
    cudaGetSymbolAddress((void**)&pB,  g_pB);
    cudaGetSymbolAddress((void**)&pP,  g_pP);
    cudaGetSymbolAddress((void**)&xkh, g_xkh); cudaGetSymbolAddress((void**)&xkl, g_xkl);
    cudaGetSymbolAddress((void**)&xvh, g_xvh); cudaGetSymbolAddress((void**)&xvl, g_xvl);
    cudaGetSymbolAddress((void**)&xrh, g_xrh); cudaGetSymbolAddress((void**)&xrl, g_xrl);
    cudaGetSymbolAddress((void**)&xfh, g_xfh); cudaGetSymbolAddress((void**)&xfl, g_xfl);
    cudaGetSymbolAddress((void**)&xgh, g_xgh); cudaGetSymbolAddress((void**)&xgl, g_xgl);
    cudaGetSymbolAddress((void**)&ryh, g_ryh); cudaGetSymbolAddress((void**)&ryl, g_ryl);
    cudaGetSymbolAddress((void**)&kkh, g_kkh); cudaGetSymbolAddress((void**)&kkl, g_kkl);
    cudaGetSymbolAddress((void**)&whk, g_whk); cudaGetSymbolAddress((void**)&wlk, g_wlk);
    cudaGetSymbolAddress((void**)&whv, g_whv); cudaGetSymbolAddress((void**)&wlv, g_wlv);
    cudaGetSymbolAddress((void**)&whr, g_whr); cudaGetSymbolAddress((void**)&wlr, g_wlr);
    cudaGetSymbolAddress((void**)&wh,  g_wh);  cudaGetSymbolAddress((void**)&wl,  g_wl);

    cudaFuncSetAttribute(mma_gemm<0>, cudaFuncAttributeMaxDynamicSharedMemorySize, SMEMSZ);
    cudaFuncSetAttribute(mma_gemm<1>, cudaFuncAttributeMaxDynamicSharedMemorySize, SMEMSZ);
    cudaFuncSetAttribute(mma_gemm<2>, cudaFuncAttributeMaxDynamicSharedMemorySize, SMEMSZ);
    cudaFuncSetAttribute(mma_gemm<3>, cudaFuncAttributeMaxDynamicSharedMemorySize, SMEMSZ);
    cudaFuncSetAttribute(mma_gemm<4>, cudaFuncAttributeMaxDynamicSharedMemorySize, SMEMSZ);

    const dim3 gA(ADIM/BN, MTOK/BM);     // (4, 64)
    const dim3 gI(IDIM/BN, MTOK/BM);     // (16, 64)
    const int scan_blks = (BSZ*NCHK*ADIM)/256;
    const int pref_blks = (BSZ*ADIM)/256;
    const int splitAH = (ADIM*HDIM/4 + 255)/256;    // 1M-elem weights
    const int splitIH = (IDIM*HDIM/4 + 255)/256;    // 4M-elem weights

    embed_ln_kernel<<<MTOK, 256>>>(ids, embed, pre_ln_w, pre_ln_b, h);

    for (int l = 0; l < LNUM; l++) {
        const size_t oH  = (size_t)l * HDIM;
        const size_t oA  = (size_t)l * ADIM;
        const size_t oAH = (size_t)l * ADIM * HDIM;
        const size_t oHA = (size_t)l * HDIM * ADIM;
        const size_t oIH = (size_t)l * IDIM * HDIM;
        const size_t oHH = (size_t)l * HDIM * HDIM;
        const size_t oHI = (size_t)l * HDIM * IDIM;

        // --- attention --- (order puts mma_gemm at this file's launch #4 -> ncu slot)
        ln_mix3_kernel<<<MTOK, 256>>>(h, ln1_w + oH, ln1_b + oH,
                                      amix_k + oH, amix_v + oH, amix_r + oH,
                                      xkh, xkl, xvh, xvl, xrh, xrl);
        split_bf16<<<splitAH, 256>>>(att_wk + oAH, whk, wlk, ADIM*HDIM/4);
        mma_gemm<0><<<gA, 256, SMEMSZ>>>(xkh, xkl, whk, wlk, nullptr, kb, nullptr, nullptr, ADIM, HDIM);
        split_bf16<<<splitAH, 256>>>(att_wv + oAH, whv, wlv, ADIM*HDIM/4);
        mma_gemm<0><<<gA, 256, SMEMSZ>>>(xvh, xvl, whv, wlv, nullptr, vb, nullptr, nullptr, ADIM, HDIM);
        split_bf16<<<splitAH, 256>>>(att_wr + oAH, whr, wlr, ADIM*HDIM/4);
        mma_gemm<0><<<gA, 256, SMEMSZ>>>(xrh, xrl, whr, wlr, nullptr, rb, nullptr, nullptr, ADIM, HDIM);
        wkv_chunk_state<<<scan_blks, 256>>>(kb, vb, tdec + oA, sA, sB, sP);
        wkv_prefix<<<pref_blks, 256>>>(sA, sB, sP, pA, pB, pP, tdec + oA);
        wkv_output<<<scan_blks, 256>>>(kb, vb, rb, pA, pB, pP, tdec + oA, tfirst + oA, ryh, ryl);
        split_bf16<<<splitAH, 256>>>(att_wo + oHA, wh, wl, HDIM*ADIM/4);
        mma_gemm<3><<<gA, 256, SMEMSZ>>>(ryh, ryl, wh, wl, nullptr, h, nullptr, nullptr, HDIM, ADIM);

        // --- feed forward ---
        ln_mix2_kernel<<<MTOK, 256>>>(h, ln2_w + oH, ln2_b + oH,
                                      fmix_k + oH, fmix_r + oH, xfh, xfl, xgh, xgl);
        split_bf16<<<splitIH, 256>>>(ffn_wk + oIH, wh, wl, IDIM*HDIM/4);
        mma_gemm<2><<<gI, 256, SMEMSZ>>>(xfh, xfl, wh, wl, nullptr, nullptr, kkh, kkl, IDIM, HDIM);
        split_bf16<<<splitAH, 256>>>(ffn_wr + oHH, whk, wlk, HDIM*HDIM/4);
        mma_gemm<1><<<gA, 256, SMEMSZ>>>(xgh, xgl, whk, wlk, nullptr, rrb, nullptr, nullptr, HDIM, HDIM);
        split_bf16<<<splitIH, 256>>>(ffn_wv + oHI, wh, wl, HDIM*IDIM/4);
        mma_gemm<4><<<gA, 256, SMEMSZ>>>(kkh, kkl, wh, wl, rrb, h, nullptr, nullptr, HDIM, IDIM);
    }

    ln_kernel<<<MTOK, 256>>>(h, post_ln_w, post_ln_b, out);
}